// round 2
// baseline (speedup 1.0000x reference)
#include <cuda_runtime.h>
#include <math.h>

#define Bc 2
#define Nc 512
#define NODEH 256
#define EDGEH 128
#define Hc 8
#define Dc 32
#define HD 256      // H*D
#define KTOT 384    // EDGEH + HD
#define TJ 64       // j-tile in edge kernel

// -------- scratch (device globals; no allocation allowed) --------
__device__ __align__(16) float g_q[Bc * Nc * HD];
__device__ __align__(16) float g_k[Bc * Nc * HD];
__device__ __align__(16) float g_v[Bc * Nc * HD];
__device__ __align__(16) float g_logits[(size_t)Bc * Nc * Hc * Nc]; // [b,i,h,j]
__device__ __align__(16) float g_Wfull[KTOT * EDGEH];               // [Wee ; Weo]
__device__ __align__(16) float g_WeSum[EDGEH * Hc];

// -------- 1) q,k,v projection: one block per (b,i) row --------
__global__ void prep_qkv_kernel(const float* __restrict__ x,
                                const float* __restrict__ Wqk,
                                const float* __restrict__ Wv,
                                const float* __restrict__ bv) {
    int row = blockIdx.x;          // b*N + i
    int t = threadIdx.x;           // 256
    __shared__ float xs[NODEH];
    xs[t] = x[(size_t)row * NODEH + t];
    __syncthreads();
    float aq = 0.f, ak = 0.f, av = 0.f;
#pragma unroll 4
    for (int m = 0; m < NODEH; m++) {
        float xv = xs[m];
        aq = fmaf(xv, Wqk[m * (2 * HD) + t], aq);
        ak = fmaf(xv, Wqk[m * (2 * HD) + HD + t], ak);
        av = fmaf(xv, Wv[m * HD + t], av);
    }
    g_q[(size_t)row * HD + t] = aq;
    g_k[(size_t)row * HD + t] = ak;
    g_v[(size_t)row * HD + t] = av + bv[t];
}

// -------- 2) Wfull = [We@Weo ; Weo], WeSum[m,h] = sum_d We[m,h*32+d] --------
__global__ void prep_w_kernel(const float* __restrict__ We,
                              const float* __restrict__ Weo) {
    int m = blockIdx.x;            // 0..383
    int c = threadIdx.x;           // 0..127
    if (m < EDGEH) {
        __shared__ float wrow[NODEH];
        wrow[c] = We[m * NODEH + c];
        wrow[c + 128] = We[m * NODEH + c + 128];
        __syncthreads();
        float acc = 0.f;
#pragma unroll 4
        for (int r = 0; r < NODEH; r++)
            acc = fmaf(wrow[r], Weo[r * EDGEH + c], acc);
        g_Wfull[m * EDGEH + c] = acc;
        if (c < Hc) {
            float s = 0.f;
#pragma unroll
            for (int d = 0; d < Dc; d++) s += wrow[c * Dc + d];
            g_WeSum[m * Hc + c] = s;
        }
    } else {
        g_Wfull[m * EDGEH + c] = Weo[(m - EDGEH) * EDGEH + c];
    }
}

// -------- 3) fused edge kernel: logits + edge_out for a (b,i) x 64-j tile ----
__global__ void edge_kernel(const float* __restrict__ ea,
                            const float* __restrict__ beo,
                            float* __restrict__ edge_out) {
    extern __shared__ float smem[];
    float* A = smem;               // [TJ][KTOT]  row = [ea_ij(128) | q_i*k_j(256)]
    float* qs = smem + TJ * KTOT;  // [HD]
    int jt = blockIdx.x;
    int bi = blockIdx.y;           // b*N + i
    int b = bi >> 9;
    int j0 = jt * TJ;
    int t = threadIdx.x;           // 256

    qs[t] = g_q[(size_t)bi * HD + t];

    // edge_attr part of A (no dependence on qs)
    const float* ea_base = ea + ((size_t)bi * Nc + j0) * EDGEH;
    for (int idx = t; idx < TJ * EDGEH; idx += 256) {
        int j = idx >> 7;
        int m = idx & 127;
        A[j * KTOT + m] = ea_base[idx];
    }
    __syncthreads();   // qs ready

    // q*k part of A
    const float* kb = g_k + ((size_t)b * Nc + j0) * HD;
    for (int idx = t; idx < TJ * HD; idx += 256) {
        int j = idx >> 8;
        int m = idx & 255;
        A[j * KTOT + EDGEH + m] = qs[m] * kb[idx];
    }
    __syncthreads();

    // attention logits for this tile: [64 j] x [8 h]
    const float inv_sqrt_d = 0.17677669529663687f;   // 1/sqrt(32)
    for (int task = t; task < TJ * Hc; task += 256) {
        int j = task >> 3;
        int h = task & 7;
        const float* Aj = A + j * KTOT;
        float s = 0.f;
#pragma unroll 4
        for (int m = 0; m < EDGEH; m++)
            s = fmaf(Aj[m], g_WeSum[m * Hc + h], s);
        float s2 = 0.f;
#pragma unroll
        for (int d = 0; d < Dc; d++) s2 += Aj[EDGEH + h * Dc + d];
        g_logits[((size_t)bi * Hc + h) * Nc + (j0 + j)] = (s + s2) * inv_sqrt_d;
    }

    // edge_out GEMM: 64j x 128c, K=384; thread = 8j x 4c micro-tile
    int tx = t & 31;               // -> c group
    int ty = t >> 5;               // -> j group (whole warp shares ty -> A broadcast)
    int c0 = tx * 4;
    float acc[8][4];
#pragma unroll
    for (int jr = 0; jr < 8; jr++)
#pragma unroll
        for (int cr = 0; cr < 4; cr++) acc[jr][cr] = 0.f;

    const float* Abase = A + (ty * 8) * KTOT;
#pragma unroll 2
    for (int m = 0; m < KTOT; m++) {
        float4 w = *(const float4*)(g_Wfull + m * EDGEH + c0);
#pragma unroll
        for (int jr = 0; jr < 8; jr++) {
            float a = Abase[jr * KTOT + m];
            acc[jr][0] = fmaf(a, w.x, acc[jr][0]);
            acc[jr][1] = fmaf(a, w.y, acc[jr][1]);
            acc[jr][2] = fmaf(a, w.z, acc[jr][2]);
            acc[jr][3] = fmaf(a, w.w, acc[jr][3]);
        }
    }
    float4 bb = *(const float4*)(beo + c0);
#pragma unroll
    for (int jr = 0; jr < 8; jr++) {
        int j = j0 + ty * 8 + jr;
        float4 o;
        o.x = acc[jr][0] + bb.x;
        o.y = acc[jr][1] + bb.y;
        o.z = acc[jr][2] + bb.z;
        o.w = acc[jr][3] + bb.w;
        *(float4*)(edge_out + ((size_t)bi * Nc + j) * EDGEH + c0) = o;
    }
}

// -------- 4) masked softmax over j; in-place on g_logits --------
// mask arrives as int32 (bool isn't a supported harness dtype)
__global__ void softmax_kernel(const int* __restrict__ mask) {
    int bih = blockIdx.x;          // (b*N+i)*8 + h
    int b = bih >> 12;             // / (N*H)
    float* row = g_logits + (size_t)bih * Nc;
    const int* mrow = mask + b * Nc;
    int t = threadIdx.x;           // 128, 4 j each
    float v[4];
    float lmax = -INFINITY;
#pragma unroll
    for (int r = 0; r < 4; r++) {
        int j = t + r * 128;
        float val = row[j];
        if (mrow[j] == 0) val = -3.402823466e38f;
        v[r] = val;
        lmax = fmaxf(lmax, val);
    }
    __shared__ float red[128];
    red[t] = lmax;
    __syncthreads();
    for (int s = 64; s > 0; s >>= 1) {
        if (t < s) red[t] = fmaxf(red[t], red[t + s]);
        __syncthreads();
    }
    float mx = red[0];
    __syncthreads();
    float lsum = 0.f;
#pragma unroll
    for (int r = 0; r < 4; r++) {
        v[r] = expf(v[r] - mx);
        lsum += v[r];
    }
    red[t] = lsum;
    __syncthreads();
    for (int s = 64; s > 0; s >>= 1) {
        if (t < s) red[t] += red[t + s];
        __syncthreads();
    }
    float inv = 1.0f / red[0];
#pragma unroll
    for (int r = 0; r < 4; r++) row[t + r * 128] = v[r] * inv;
}

// -------- 5) node path: ctx = att @ v, node_out = ctx @ Wno + bno --------
__global__ void node_kernel(const float* __restrict__ Wno,
                            const float* __restrict__ bno,
                            float* __restrict__ node_out) {
    __shared__ float att_s[Hc * Nc];  // 16 KB
    __shared__ float ctx_s[HD];
    int bi = blockIdx.x;
    int b = bi >> 9;
    int t = threadIdx.x;              // 256, t == m == h*32+d
    const float* lg = g_logits + (size_t)bi * Hc * Nc;
    for (int idx = t; idx < Hc * Nc; idx += 256) att_s[idx] = lg[idx];
    __syncthreads();
    int h = t >> 5;
    const float* vb = g_v + (size_t)b * Nc * HD + t;
    float acc = 0.f;
#pragma unroll 4
    for (int j = 0; j < Nc; j++)
        acc = fmaf(att_s[h * Nc + j], vb[(size_t)j * HD], acc);
    ctx_s[t] = acc;
    __syncthreads();
    float o = bno[t];
#pragma unroll 4
    for (int m = 0; m < HD; m++)
        o = fmaf(ctx_s[m], Wno[m * HD + t], o);
    node_out[(size_t)bi * HD + t] = o;
}

extern "C" void kernel_launch(void* const* d_in, const int* in_sizes, int n_in,
                              void* d_out, int out_size) {
    const float* x    = (const float*)d_in[0];
    const float* ea   = (const float*)d_in[1];
    const int*   mask = (const int*)d_in[2];
    const float* Wqk  = (const float*)d_in[3];
    const float* We   = (const float*)d_in[4];
    const float* Wv   = (const float*)d_in[5];
    const float* bv   = (const float*)d_in[6];
    const float* Wno  = (const float*)d_in[7];
    const float* bno  = (const float*)d_in[8];
    const float* Weo  = (const float*)d_in[9];
    const float* beo  = (const float*)d_in[10];

    float* out = (float*)d_out;
    float* node_out = out;                                  // [B,N,256]
    float* edge_out = out + (size_t)Bc * Nc * NODEH;        // [B,N,N,128]

    const int smem_edge = (TJ * KTOT + HD) * (int)sizeof(float);  // 99328 B
    cudaFuncSetAttribute(edge_kernel,
                         cudaFuncAttributeMaxDynamicSharedMemorySize, smem_edge);

    prep_qkv_kernel<<<Bc * Nc, 256>>>(x, Wqk, Wv, bv);
    prep_w_kernel<<<KTOT, 128>>>(We, Weo);
    dim3 eg(Nc / TJ, Bc * Nc);
    edge_kernel<<<eg, 256, smem_edge>>>(ea, beo, edge_out);
    softmax_kernel<<<Bc * Nc * Hc, 128>>>(mask);
    node_kernel<<<Bc * Nc, 256>>>(Wno, bno, node_out);
}

// round 6
// speedup vs baseline: 2.3649x; 2.3649x over previous
#include <cuda_runtime.h>
#include <cuda_bf16.h>
#include <cstdint>
#include <math.h>

#define Bc 2
#define Nc 512
#define NODEH 256
#define EDGEH 128
#define Hc 8
#define Dc 32
#define HD 256
#define KTOT 384     // EDGEH + HD
#define NB 136       // GEMM N: 128 edge cols + 8 logit cols
#define NKSTEP 24    // KTOT / 16
#define NTILES 17    // NB / 8

// ---------------- scratch globals ----------------
__device__ __align__(16) float g_q[Bc * Nc * HD];
__device__ __align__(16) float g_k[Bc * Nc * HD];
__device__ __align__(16) float g_v[Bc * Nc * HD];
__device__ __align__(16) float g_logits[(size_t)Bc * Nc * Hc * Nc]; // [b,i,h,j]
// W in mma B-fragment layout: [kstep][ntile][lane] = {hi_b0, hi_b1, lo_b0, lo_b1}
__device__ __align__(16) uint4 g_WBfrag[NKSTEP * NTILES * 32];

// ---------------- helpers ----------------
__device__ __forceinline__ uint32_t smem_u32(const void* p) {
    uint32_t a;
    asm("{ .reg .u64 t; cvta.to.shared.u64 t, %1; cvt.u32.u64 %0, t; }" : "=r"(a) : "l"(p));
    return a;
}
__device__ __forceinline__ void ldsm4(uint32_t* r, uint32_t addr) {
    asm volatile("ldmatrix.sync.aligned.m8n8.x4.shared.b16 {%0,%1,%2,%3}, [%4];"
        : "=r"(r[0]), "=r"(r[1]), "=r"(r[2]), "=r"(r[3]) : "r"(addr));
}
__device__ __forceinline__ void mma_bf16(float* c, const uint32_t* a, uint32_t b0, uint32_t b1) {
    asm volatile("mma.sync.aligned.m16n8k16.row.col.f32.bf16.bf16.f32 "
        "{%0,%1,%2,%3}, {%4,%5,%6,%7}, {%8,%9}, {%0,%1,%2,%3};"
        : "+f"(c[0]), "+f"(c[1]), "+f"(c[2]), "+f"(c[3])
        : "r"(a[0]), "r"(a[1]), "r"(a[2]), "r"(a[3]), "r"(b0), "r"(b1));
}

// ---------------- edge kernel smem layout (bytes) ----------------
// A planes: 256 rows x 64 k bf16, row stride 144B (128B data + 16B pad)
#define ASTRIDE 144
#define A_HI 0                          // 36864
#define A_LO 36864                      // 36864 -> 73728
#define WS_OFF 73728                    // 17*32*16*4 ksteps = 34816 -> 108544
#define QS_OFF 108544                   // 256 f32 -> 109568
#define BEO_OFF 109568                  // 128 f32 -> 110080
#define SMEM_EDGE 110080

// ======== 1) q,k,v projection: 4 rows per block ========
__global__ void prep_qkv_kernel(const float* __restrict__ x,
                                const float* __restrict__ Wqk,
                                const float* __restrict__ Wv,
                                const float* __restrict__ bv) {
    __shared__ float xs[4 * NODEH];
    int r0 = blockIdx.x * 4;
    int t = threadIdx.x;
#pragma unroll
    for (int r = 0; r < 4; r++) xs[r * NODEH + t] = x[(size_t)(r0 + r) * NODEH + t];
    __syncthreads();
    float aq[4] = {0, 0, 0, 0}, ak[4] = {0, 0, 0, 0}, av[4] = {0, 0, 0, 0};
#pragma unroll 2
    for (int m = 0; m < NODEH; m++) {
        float wq = Wqk[m * (2 * HD) + t];
        float wk = Wqk[m * (2 * HD) + HD + t];
        float wv = Wv[m * HD + t];
#pragma unroll
        for (int r = 0; r < 4; r++) {
            float xv = xs[r * NODEH + m];
            aq[r] = fmaf(xv, wq, aq[r]);
            ak[r] = fmaf(xv, wk, ak[r]);
            av[r] = fmaf(xv, wv, av[r]);
        }
    }
    float bvt = bv[t];
#pragma unroll
    for (int r = 0; r < 4; r++) {
        g_q[(size_t)(r0 + r) * HD + t] = aq[r];
        g_k[(size_t)(r0 + r) * HD + t] = ak[r];
        g_v[(size_t)(r0 + r) * HD + t] = av[r] + bvt;
    }
}

// ======== 2) W frag pack: B[k][n]; n<128: [Wee;Weo] col; n=128+h: logit col ====
__global__ void prep_w_kernel(const float* __restrict__ We,
                              const float* __restrict__ Weo) {
    __shared__ float wrow[NODEH];
    int k = blockIdx.x;            // 0..383
    int n = threadIdx.x;           // 0..159 (136 active)
    if (k < EDGEH) {
        if (n < 128) { wrow[n] = We[k * NODEH + n]; wrow[n + 128] = We[k * NODEH + n + 128]; }
        __syncthreads();
    }
    if (n >= NB) return;
    float w;
    if (n < 128) {
        if (k < EDGEH) {
            float acc = 0.f;
#pragma unroll 4
            for (int r = 0; r < NODEH; r++) acc = fmaf(wrow[r], Weo[r * EDGEH + n], acc);
            w = acc;                       // (We@Weo)[k][n]
        } else {
            w = Weo[(k - EDGEH) * EDGEH + n];
        }
    } else {
        int h = n - 128;
        if (k < EDGEH) {
            float s = 0.f;
#pragma unroll
            for (int d = 0; d < Dc; d++) s += wrow[h * Dc + d];
            w = s;                         // WeSum[k][h]
        } else {
            w = (((k - EDGEH) >> 5) == h) ? 1.0f : 0.0f;  // indicator for q*k sum
        }
    }
    // split hi/lo
    uint32_t bits = __float_as_uint(w);
    uint32_t hib = bits & 0xffff0000u;
    float lo = w - __uint_as_float(hib);
    unsigned short hi16 = (unsigned short)(hib >> 16);
    unsigned short lo16 = __bfloat16_as_ushort(__float2bfloat16(lo));
    // fragment placement (m16n8k16 B operand)
    int kstep = k >> 4, kk = k & 15;
    int reg = kk >> 3, tig = (kk & 7) >> 1, kpar = kk & 1;
    int ntile = n >> 3;
    int lane = (n & 7) * 4 + tig;
    size_t base = (((size_t)kstep * NTILES + ntile) * 32 + lane) * 8;
    unsigned short* W16 = (unsigned short*)g_WBfrag;
    W16[base + reg * 2 + kpar] = hi16;
    W16[base + 4 + reg * 2 + kpar] = lo16;
}

// ======== 3) edge kernel: HMMA bf16 3-term split, logits folded as N-cols ====
__global__ void __launch_bounds__(512, 1)
edge_kernel(const float* __restrict__ ea,
            const float* __restrict__ beo,
            float* __restrict__ edge_out) {
    extern __shared__ char smem[];
    uint32_t sb = smem_u32(smem);
    int t = threadIdx.x;
    int lane = t & 31;
    int w = t >> 5;
    int blk = blockIdx.x;
    int bi = blk >> 1;             // b*N + i
    int half = blk & 1;
    int b = bi >> 9;
    int rg = w >> 1;               // row group 0..7 (32 rows each)
    int cg = w & 1;                // col group: ntiles [cg*8, cg*8+8]
    int ntbase = cg * 8;
    int jg0 = half * 256;

    if (t < 256) ((float*)(smem + QS_OFF))[t] = g_q[(size_t)bi * HD + t];
    else if (t < 384) ((float*)(smem + BEO_OFF))[t - 256] = beo[t - 256];

    float acc[2][9][4];
#pragma unroll
    for (int mt = 0; mt < 2; mt++)
#pragma unroll
        for (int nt = 0; nt < 9; nt++)
#pragma unroll
            for (int e = 0; e < 4; e++) acc[mt][nt][e] = 0.f;

    // ldmatrix source addresses (x4: rows 0-15, k halves 0/8)
    uint32_t arow = (uint32_t)(rg * 32 + (lane & 15));
    uint32_t kx = (uint32_t)((lane >> 4) * 16);
    uint32_t ahi_base = sb + A_HI + arow * ASTRIDE + kx;
    uint32_t alo_base = sb + A_LO + arow * ASTRIDE + kx;

    int row_b = t >> 2;            // 0..127
    int kq = t & 3;                // 16-k slice

    for (int c = 0; c < 6; c++) {
        // ---- W chunk copy: 4 ksteps of frags -> smem ----
        {
            const uint4* src = g_WBfrag + c * (4 * NTILES * 32);
            uint4* dst = (uint4*)(smem + WS_OFF);
            for (int i = t; i < 4 * NTILES * 32; i += 512) dst[i] = src[i];
        }
        // ---- A build: 256 rows x 64 k, split bf16 hi/lo ----
#pragma unroll
        for (int p = 0; p < 2; p++) {
            int row = row_b + p * 128;
            float a[16];
            if (c < 2) {
                const float4* s = (const float4*)(ea +
                    ((size_t)(bi * 512 + jg0 + row) * EDGEH + c * 64 + kq * 16));
#pragma unroll
                for (int q = 0; q < 4; q++) {
                    float4 v = s[q];
                    a[4 * q] = v.x; a[4 * q + 1] = v.y; a[4 * q + 2] = v.z; a[4 * q + 3] = v.w;
                }
            } else {
                int m0 = (c - 2) * 64 + kq * 16;
                const float4* s = (const float4*)(g_k +
                    (size_t)(b * 512 + jg0 + row) * HD + m0);
                const float* qp = (const float*)(smem + QS_OFF) + m0;
#pragma unroll
                for (int q = 0; q < 4; q++) {
                    float4 v = s[q];
                    a[4 * q]     = qp[4 * q]     * v.x;
                    a[4 * q + 1] = qp[4 * q + 1] * v.y;
                    a[4 * q + 2] = qp[4 * q + 2] * v.z;
                    a[4 * q + 3] = qp[4 * q + 3] * v.w;
                }
            }
            uint32_t off = (uint32_t)(row * ASTRIDE + kq * 32);
#pragma unroll
            for (int e = 0; e < 16; e += 2) {
                uint32_t b0 = __float_as_uint(a[e]) & 0xffff0000u;
                uint32_t b1 = __float_as_uint(a[e + 1]) & 0xffff0000u;
                uint32_t hp = (b0 >> 16) | b1;
                float l0 = a[e] - __uint_as_float(b0);
                float l1 = a[e + 1] - __uint_as_float(b1);
                __nv_bfloat162 lp = __floats2bfloat162_rn(l0, l1);
                uint32_t lo32 = *reinterpret_cast<uint32_t*>(&lp);
                *(uint32_t*)(smem + A_HI + off + e * 2) = hp;
                *(uint32_t*)(smem + A_LO + off + e * 2) = lo32;
            }
        }
        __syncthreads();
        // ---- MMA over 4 ksteps ----
#pragma unroll
        for (int ks = 0; ks < 4; ks++) {
            uint32_t ah0[4], ah1[4], al0[4], al1[4];
            ldsm4(ah0, ahi_base + ks * 32);
            ldsm4(ah1, ahi_base + 16 * ASTRIDE + ks * 32);
            ldsm4(al0, alo_base + ks * 32);
            ldsm4(al1, alo_base + 16 * ASTRIDE + ks * 32);
#pragma unroll
            for (int nt = 0; nt < 9; nt++) {
                uint4 wb = *(const uint4*)(smem + WS_OFF +
                    (((ks * NTILES) + ntbase + nt) * 32 + lane) * 16);
                mma_bf16(acc[0][nt], ah0, wb.x, wb.y);
                mma_bf16(acc[1][nt], ah1, wb.x, wb.y);
                mma_bf16(acc[0][nt], al0, wb.x, wb.y);
                mma_bf16(acc[1][nt], al1, wb.x, wb.y);
                mma_bf16(acc[0][nt], ah0, wb.z, wb.w);
                mma_bf16(acc[1][nt], ah1, wb.z, wb.w);
            }
        }
        __syncthreads();
    }

    // ---- epilogue ----
    const float* bs = (const float*)(smem + BEO_OFF);
    int jr = rg * 32 + (lane >> 2);
    int cl = (lane & 3) * 2;
    const float isd = 0.17677669529663687f;   // 1/sqrt(32)
#pragma unroll
    for (int mt = 0; mt < 2; mt++) {
        int j = jg0 + jr + mt * 16;
#pragma unroll
        for (int nt = 0; nt < 9; nt++) {
            if (cg == 1 && nt == 0) continue;   // tile 8 duplicated; cg0 stores it
            int gnt = ntbase + nt;
            if (gnt < 16) {
                int col = gnt * 8 + cl;
                float2 o0, o1;
                o0.x = acc[mt][nt][0] + bs[col];
                o0.y = acc[mt][nt][1] + bs[col + 1];
                o1.x = acc[mt][nt][2] + bs[col];
                o1.y = acc[mt][nt][3] + bs[col + 1];
                *(float2*)(edge_out + ((size_t)bi * 512 + j) * EDGEH + col) = o0;
                *(float2*)(edge_out + ((size_t)bi * 512 + j + 8) * EDGEH + col) = o1;
            } else {
                int h0 = cl, h1 = cl + 1;
                g_logits[((size_t)bi * Hc + h0) * Nc + j] = acc[mt][nt][0] * isd;
                g_logits[((size_t)bi * Hc + h1) * Nc + j] = acc[mt][nt][1] * isd;
                g_logits[((size_t)bi * Hc + h0) * Nc + j + 8] = acc[mt][nt][2] * isd;
                g_logits[((size_t)bi * Hc + h1) * Nc + j + 8] = acc[mt][nt][3] * isd;
            }
        }
    }
}

// ======== 4) masked softmax over j (mask is int32) ========
__global__ void softmax_kernel(const int* __restrict__ mask) {
    int bih = blockIdx.x;
    int b = bih >> 12;
    float* row = g_logits + (size_t)bih * Nc;
    const int* mrow = mask + b * Nc;
    int t = threadIdx.x;
    float v[4];
    float lmax = -INFINITY;
#pragma unroll
    for (int r = 0; r < 4; r++) {
        int j = t + r * 128;
        float val = row[j];
        if (mrow[j] == 0) val = -3.402823466e38f;
        v[r] = val;
        lmax = fmaxf(lmax, val);
    }
    __shared__ float red[128];
    red[t] = lmax;
    __syncthreads();
    for (int s = 64; s > 0; s >>= 1) {
        if (t < s) red[t] = fmaxf(red[t], red[t + s]);
        __syncthreads();
    }
    float mx = red[0];
    __syncthreads();
    float lsum = 0.f;
#pragma unroll
    for (int r = 0; r < 4; r++) { v[r] = expf(v[r] - mx); lsum += v[r]; }
    red[t] = lsum;
    __syncthreads();
    for (int s = 64; s > 0; s >>= 1) {
        if (t < s) red[t] += red[t + s];
        __syncthreads();
    }
    float inv = 1.0f / red[0];
#pragma unroll
    for (int r = 0; r < 4; r++) row[t + r * 128] = v[r] * inv;
}

// ======== 5) node path: 4 i-rows per block ========
__global__ void node_kernel(const float* __restrict__ Wno,
                            const float* __restrict__ bno,
                            float* __restrict__ node_out) {
    extern __shared__ float ns[];          // att 4*4096 + ctx 4*256
    float* att_s = ns;
    float* ctx_s = ns + 4 * Hc * Nc;
    int i0 = blockIdx.x * 4;
    int b = i0 >> 9;
    int t = threadIdx.x;
    const float* lg = g_logits + (size_t)i0 * Hc * Nc;
    for (int idx = t; idx < 4 * Hc * Nc; idx += 256) att_s[idx] = lg[idx];
    __syncthreads();
    int h = t >> 5;
    const float* vb = g_v + (size_t)b * Nc * HD + t;
    float a0 = 0, a1 = 0, a2 = 0, a3 = 0;
#pragma unroll 2
    for (int j = 0; j < Nc; j++) {
        float v = vb[(size_t)j * HD];
        a0 = fmaf(att_s[h * Nc + j], v, a0);
        a1 = fmaf(att_s[4096 + h * Nc + j], v, a1);
        a2 = fmaf(att_s[8192 + h * Nc + j], v, a2);
        a3 = fmaf(att_s[12288 + h * Nc + j], v, a3);
    }
    ctx_s[t] = a0; ctx_s[256 + t] = a1; ctx_s[512 + t] = a2; ctx_s[768 + t] = a3;
    __syncthreads();
    float bb = bno[t];
    float o0 = bb, o1 = bb, o2 = bb, o3 = bb;
#pragma unroll 2
    for (int m = 0; m < HD; m++) {
        float ww = Wno[m * HD + t];
        o0 = fmaf(ctx_s[m], ww, o0);
        o1 = fmaf(ctx_s[256 + m], ww, o1);
        o2 = fmaf(ctx_s[512 + m], ww, o2);
        o3 = fmaf(ctx_s[768 + m], ww, o3);
    }
    node_out[(size_t)i0 * HD + t] = o0;
    node_out[(size_t)(i0 + 1) * HD + t] = o1;
    node_out[(size_t)(i0 + 2) * HD + t] = o2;
    node_out[(size_t)(i0 + 3) * HD + t] = o3;
}

extern "C" void kernel_launch(void* const* d_in, const int* in_sizes, int n_in,
                              void* d_out, int out_size) {
    const float* x    = (const float*)d_in[0];
    const float* ea   = (const float*)d_in[1];
    const int*   mask = (const int*)d_in[2];
    const float* Wqk  = (const float*)d_in[3];
    const float* We   = (const float*)d_in[4];
    const float* Wv   = (const float*)d_in[5];
    const float* bv   = (const float*)d_in[6];
    const float* Wno  = (const float*)d_in[7];
    const float* bno  = (const float*)d_in[8];
    const float* Weo  = (const float*)d_in[9];
    const float* beo  = (const float*)d_in[10];

    float* out = (float*)d_out;
    float* node_out = out;
    float* edge_out = out + (size_t)Bc * Nc * NODEH;

    cudaFuncSetAttribute(edge_kernel, cudaFuncAttributeMaxDynamicSharedMemorySize, SMEM_EDGE);
    cudaFuncSetAttribute(node_kernel, cudaFuncAttributeMaxDynamicSharedMemorySize,
                         (4 * Hc * Nc + 4 * HD) * (int)sizeof(float));

    prep_qkv_kernel<<<Bc * Nc / 4, 256>>>(x, Wqk, Wv, bv);
    prep_w_kernel<<<KTOT, 160>>>(We, Weo);
    edge_kernel<<<Bc * Nc * 2, 512, SMEM_EDGE>>>(ea, beo, edge_out);
    softmax_kernel<<<Bc * Nc * Hc, 128>>>(mask);
    node_kernel<<<Bc * Nc / 4, 256, (4 * Hc * Nc + 4 * HD) * (int)sizeof(float)>>>(Wno, bno, node_out);
}

// round 8
// speedup vs baseline: 2.8063x; 1.1866x over previous
#include <cuda_runtime.h>
#include <cuda_bf16.h>
#include <cuda_fp16.h>
#include <cstdint>
#include <math.h>

#define Bc 2
#define Nc 512
#define NODEH 256
#define EDGEH 128
#define Hc 8
#define Dc 32
#define HD 256
#define KTOT 384     // EDGEH + HD
#define NB 136       // GEMM N: 128 edge cols + 8 logit cols
#define NKSTEP 24    // KTOT / 16
#define NTILES 17    // NB / 8

// ---------------- scratch globals ----------------
__device__ __align__(16) float g_q[Bc * Nc * HD];
__device__ __align__(16) float g_k[Bc * Nc * HD];
__device__ __align__(16) float g_v[Bc * Nc * HD];
__device__ __align__(16) float g_logits[(size_t)Bc * Nc * Hc * Nc]; // [b,i,h,j]
// W in mma B-fragment layout: [kstep][ntile][lane] = {wh_b0, wh_b1, wl_b0, wl_b1} (fp16)
__device__ __align__(16) uint4 g_WBfrag[NKSTEP * NTILES * 32];

// ---------------- helpers ----------------
__device__ __forceinline__ uint32_t smem_u32(const void* p) {
    uint32_t a;
    asm("{ .reg .u64 t; cvta.to.shared.u64 t, %1; cvt.u32.u64 %0, t; }" : "=r"(a) : "l"(p));
    return a;
}
__device__ __forceinline__ void ldsm4(uint32_t* r, uint32_t addr) {
    asm volatile("ldmatrix.sync.aligned.m8n8.x4.shared.b16 {%0,%1,%2,%3}, [%4];"
        : "=r"(r[0]), "=r"(r[1]), "=r"(r[2]), "=r"(r[3]) : "r"(addr));
}
__device__ __forceinline__ void mma_f16(float* c, const uint32_t* a, uint32_t b0, uint32_t b1) {
    asm volatile("mma.sync.aligned.m16n8k16.row.col.f32.f16.f16.f32 "
        "{%0,%1,%2,%3}, {%4,%5,%6,%7}, {%8,%9}, {%0,%1,%2,%3};"
        : "+f"(c[0]), "+f"(c[1]), "+f"(c[2]), "+f"(c[3])
        : "r"(a[0]), "r"(a[1]), "r"(a[2]), "r"(a[3]), "r"(b0), "r"(b1));
}

// ---------------- edge kernel smem layout (bytes) ----------------
// A plane: 128 rows x 64 k fp16, row stride 144B (128B data + 16B pad)
#define ASTRIDE 144
#define A_OFF 0                         // 18432
#define WS_OFF 18432                    // 17*32*16B*4 ksteps = 34816 -> 53248
#define QS_OFF 53248                    // 256 f32 -> 54272
#define BEO_OFF 54272                   // 128 f32 -> 54784
#define SMEM_EDGE 54784

// ======== 1) q,k,v projection: 4 rows per block ========
__global__ void prep_qkv_kernel(const float* __restrict__ x,
                                const float* __restrict__ Wqk,
                                const float* __restrict__ Wv,
                                const float* __restrict__ bv) {
    __shared__ float xs[4 * NODEH];
    int r0 = blockIdx.x * 4;
    int t = threadIdx.x;
#pragma unroll
    for (int r = 0; r < 4; r++) xs[r * NODEH + t] = x[(size_t)(r0 + r) * NODEH + t];
    __syncthreads();
    float aq[4] = {0, 0, 0, 0}, ak[4] = {0, 0, 0, 0}, av[4] = {0, 0, 0, 0};
#pragma unroll 2
    for (int m = 0; m < NODEH; m++) {
        float wq = Wqk[m * (2 * HD) + t];
        float wk = Wqk[m * (2 * HD) + HD + t];
        float wv = Wv[m * HD + t];
#pragma unroll
        for (int r = 0; r < 4; r++) {
            float xv = xs[r * NODEH + m];
            aq[r] = fmaf(xv, wq, aq[r]);
            ak[r] = fmaf(xv, wk, ak[r]);
            av[r] = fmaf(xv, wv, av[r]);
        }
    }
    float bvt = bv[t];
#pragma unroll
    for (int r = 0; r < 4; r++) {
        g_q[(size_t)(r0 + r) * HD + t] = aq[r];
        g_k[(size_t)(r0 + r) * HD + t] = ak[r];
        g_v[(size_t)(r0 + r) * HD + t] = av[r] + bvt;
    }
}

// ======== 2) W frag pack: B[k][n]; n<128: [Wee;Weo] col; n=128+h: logit col ====
// fp16 exact split: W = W_h + W_l (both fp16)
__global__ void prep_w_kernel(const float* __restrict__ We,
                              const float* __restrict__ Weo) {
    __shared__ float wrow[NODEH];
    int k = blockIdx.x;            // 0..383
    int n = threadIdx.x;           // 0..159 (136 active)
    if (k < EDGEH) {
        if (n < 128) { wrow[n] = We[k * NODEH + n]; wrow[n + 128] = We[k * NODEH + n + 128]; }
        __syncthreads();
    }
    if (n >= NB) return;
    float w;
    if (n < 128) {
        if (k < EDGEH) {
            float acc = 0.f;
#pragma unroll 4
            for (int r = 0; r < NODEH; r++) acc = fmaf(wrow[r], Weo[r * EDGEH + n], acc);
            w = acc;                       // (We@Weo)[k][n]
        } else {
            w = Weo[(k - EDGEH) * EDGEH + n];
        }
    } else {
        int h = n - 128;
        if (k < EDGEH) {
            float s = 0.f;
#pragma unroll
            for (int d = 0; d < Dc; d++) s += wrow[h * Dc + d];
            w = s;                         // WeSum[k][h]
        } else {
            w = (((k - EDGEH) >> 5) == h) ? 1.0f : 0.0f;  // indicator for q*k sum
        }
    }
    // fp16 hi/lo split
    __half wh = __float2half_rn(w);
    float wl = w - __half2float(wh);
    unsigned short hi16 = __half_as_ushort(wh);
    unsigned short lo16 = __half_as_ushort(__float2half_rn(wl));
    // fragment placement (m16n8k16 B operand)
    int kstep = k >> 4, kk = k & 15;
    int reg = kk >> 3, tig = (kk & 7) >> 1, kpar = kk & 1;
    int ntile = n >> 3;
    int lane = (n & 7) * 4 + tig;
    size_t base = (((size_t)kstep * NTILES + ntile) * 32 + lane) * 8;
    unsigned short* W16 = (unsigned short*)g_WBfrag;
    W16[base + reg * 2 + kpar] = hi16;
    W16[base + 4 + reg * 2 + kpar] = lo16;
}

// ======== 3) edge kernel: HMMA fp16 2-product (W split), logits as N-cols ====
__global__ void __launch_bounds__(256, 2)
edge_kernel(const float* __restrict__ ea,
            const float* __restrict__ beo,
            float* __restrict__ edge_out) {
    extern __shared__ char smem[];
    uint32_t sb = smem_u32(smem);
    int t = threadIdx.x;
    int lane = t & 31;
    int w = t >> 5;                // 0..7
    int blk = blockIdx.x;
    int bi = blk >> 2;             // b*N + i
    int quarter = blk & 3;
    int b = bi >> 9;
    int rg = w >> 1;               // row group 0..3 (32 rows each)
    int cg = w & 1;                // col group
    int ntbase = cg * 8;
    int jg0 = quarter * 128;

    if (t < 256) ((float*)(smem + QS_OFF))[t] = g_q[(size_t)bi * HD + t];
    if (t < 128) ((float*)(smem + BEO_OFF))[t] = beo[t];

    float acc[2][9][4];
#pragma unroll
    for (int mt = 0; mt < 2; mt++)
#pragma unroll
        for (int nt = 0; nt < 9; nt++)
#pragma unroll
            for (int e = 0; e < 4; e++) acc[mt][nt][e] = 0.f;

    // ldmatrix source addresses (x4: 16 rows, two 8-elem k halves)
    uint32_t arow = (uint32_t)(rg * 32 + (lane & 15));
    uint32_t kx = (uint32_t)((lane >> 4) * 16);    // BYTE offset: 8 fp16 = 16B
    uint32_t a_base = sb + A_OFF + arow * ASTRIDE + kx;

    int row_b = t >> 1;            // 0..127
    int kq = t & 1;                // 32-k half

    for (int c = 0; c < 6; c++) {
        // ---- W chunk copy: 4 ksteps of frags -> smem ----
        {
            const uint4* src = g_WBfrag + c * (4 * NTILES * 32);
            uint4* dst = (uint4*)(smem + WS_OFF);
            for (int i = t; i < 4 * NTILES * 32; i += 256) dst[i] = src[i];
        }
        // ---- A build: 128 rows x 64 k, fp16 quantize ----
        {
            float a[32];
            if (c < 2) {
                const float4* s = (const float4*)(ea +
                    ((size_t)(bi * 512 + jg0 + row_b) * EDGEH + c * 64 + kq * 32));
#pragma unroll
                for (int q = 0; q < 8; q++) {
                    float4 v = s[q];
                    a[4 * q] = v.x; a[4 * q + 1] = v.y; a[4 * q + 2] = v.z; a[4 * q + 3] = v.w;
                }
            } else {
                int m0 = (c - 2) * 64 + kq * 32;
                const float4* s = (const float4*)(g_k +
                    (size_t)(b * 512 + jg0 + row_b) * HD + m0);
                const float* qp = (const float*)(smem + QS_OFF) + m0;
#pragma unroll
                for (int q = 0; q < 8; q++) {
                    float4 v = s[q];
                    a[4 * q]     = qp[4 * q]     * v.x;
                    a[4 * q + 1] = qp[4 * q + 1] * v.y;
                    a[4 * q + 2] = qp[4 * q + 2] * v.z;
                    a[4 * q + 3] = qp[4 * q + 3] * v.w;
                }
            }
            uint32_t off = (uint32_t)(row_b * ASTRIDE + kq * 64);
#pragma unroll
            for (int e = 0; e < 32; e += 2) {
                __half2 hp = __floats2half2_rn(a[e], a[e + 1]);
                *(uint32_t*)(smem + A_OFF + off + e * 2) = *reinterpret_cast<uint32_t*>(&hp);
            }
        }
        __syncthreads();
        // ---- MMA over 4 ksteps: acc += A*(Wh + Wl) ----
#pragma unroll
        for (int ks = 0; ks < 4; ks++) {
            uint32_t a0[4], a1[4];
            ldsm4(a0, a_base + ks * 32);
            ldsm4(a1, a_base + 16 * ASTRIDE + ks * 32);
#pragma unroll
            for (int nt = 0; nt < 9; nt++) {
                if (cg == 0 && nt == 8) continue;   // ntile 8 handled by cg1
                uint4 wb = *(const uint4*)(smem + WS_OFF +
                    (((ks * NTILES) + ntbase + nt) * 32 + lane) * 16);
                mma_f16(acc[0][nt], a0, wb.x, wb.y);
                mma_f16(acc[1][nt], a1, wb.x, wb.y);
                mma_f16(acc[0][nt], a0, wb.z, wb.w);
                mma_f16(acc[1][nt], a1, wb.z, wb.w);
            }
        }
        __syncthreads();
    }

    // ---- epilogue ----
    const float* bs = (const float*)(smem + BEO_OFF);
    int jr = rg * 32 + (lane >> 2);
    int cl = (lane & 3) * 2;
    const float isd = 0.17677669529663687f;   // 1/sqrt(32)
#pragma unroll
    for (int mt = 0; mt < 2; mt++) {
        int j = jg0 + jr + mt * 16;
#pragma unroll
        for (int nt = 0; nt < 9; nt++) {
            if (cg == 0 && nt == 8) continue;
            int gnt = ntbase + nt;
            if (gnt < 16) {
                int col = gnt * 8 + cl;
                float2 o0, o1;
                o0.x = acc[mt][nt][0] + bs[col];
                o0.y = acc[mt][nt][1] + bs[col + 1];
                o1.x = acc[mt][nt][2] + bs[col];
                o1.y = acc[mt][nt][3] + bs[col + 1];
                *(float2*)(edge_out + ((size_t)bi * 512 + j) * EDGEH + col) = o0;
                *(float2*)(edge_out + ((size_t)bi * 512 + j + 8) * EDGEH + col) = o1;
            } else {
                int h0 = cl, h1 = cl + 1;
                g_logits[((size_t)bi * Hc + h0) * Nc + j] = acc[mt][nt][0] * isd;
                g_logits[((size_t)bi * Hc + h1) * Nc + j] = acc[mt][nt][1] * isd;
                g_logits[((size_t)bi * Hc + h0) * Nc + j + 8] = acc[mt][nt][2] * isd;
                g_logits[((size_t)bi * Hc + h1) * Nc + j + 8] = acc[mt][nt][3] * isd;
            }
        }
    }
}

// ======== 4) masked softmax over j (mask is int32) ========
__global__ void softmax_kernel(const int* __restrict__ mask) {
    int bih = blockIdx.x;
    int b = bih >> 12;
    float* row = g_logits + (size_t)bih * Nc;
    const int* mrow = mask + b * Nc;
    int t = threadIdx.x;
    float v[4];
    float lmax = -INFINITY;
#pragma unroll
    for (int r = 0; r < 4; r++) {
        int j = t + r * 128;
        float val = row[j];
        if (mrow[j] == 0) val = -3.402823466e38f;
        v[r] = val;
        lmax = fmaxf(lmax, val);
    }
    __shared__ float red[128];
    red[t] = lmax;
    __syncthreads();
    for (int s = 64; s > 0; s >>= 1) {
        if (t < s) red[t] = fmaxf(red[t], red[t + s]);
        __syncthreads();
    }
    float mx = red[0];
    __syncthreads();
    float lsum = 0.f;
#pragma unroll
    for (int r = 0; r < 4; r++) { v[r] = expf(v[r] - mx); lsum += v[r]; }
    red[t] = lsum;
    __syncthreads();
    for (int s = 64; s > 0; s >>= 1) {
        if (t < s) red[t] += red[t + s];
        __syncthreads();
    }
    float inv = 1.0f / red[0];
#pragma unroll
    for (int r = 0; r < 4; r++) row[t + r * 128] = v[r] * inv;
}

// ======== 5) node path: 4 i-rows per block ========
__global__ void node_kernel(const float* __restrict__ Wno,
                            const float* __restrict__ bno,
                            float* __restrict__ node_out) {
    extern __shared__ float ns[];          // att 4*4096 + ctx 4*256
    float* att_s = ns;
    float* ctx_s = ns + 4 * Hc * Nc;
    int i0 = blockIdx.x * 4;
    int b = i0 >> 9;
    int t = threadIdx.x;
    const float* lg = g_logits + (size_t)i0 * Hc * Nc;
    for (int idx = t; idx < 4 * Hc * Nc; idx += 256) att_s[idx] = lg[idx];
    __syncthreads();
    int h = t >> 5;
    const float* vb = g_v + (size_t)b * Nc * HD + t;
    float a0 = 0, a1 = 0, a2 = 0, a3 = 0;
#pragma unroll 2
    for (int j = 0; j < Nc; j++) {
        float v = vb[(size_t)j * HD];
        a0 = fmaf(att_s[h * Nc + j], v, a0);
        a1 = fmaf(att_s[4096 + h * Nc + j], v, a1);
        a2 = fmaf(att_s[8192 + h * Nc + j], v, a2);
        a3 = fmaf(att_s[12288 + h * Nc + j], v, a3);
    }
    ctx_s[t] = a0; ctx_s[256 + t] = a1; ctx_s[512 + t] = a2; ctx_s[768 + t] = a3;
    __syncthreads();
    float bb = bno[t];
    float o0 = bb, o1 = bb, o2 = bb, o3 = bb;
#pragma unroll 2
    for (int m = 0; m < HD; m++) {
        float ww = Wno[m * HD + t];
        o0 = fmaf(ctx_s[m], ww, o0);
        o1 = fmaf(ctx_s[256 + m], ww, o1);
        o2 = fmaf(ctx_s[512 + m], ww, o2);
        o3 = fmaf(ctx_s[768 + m], ww, o3);
    }
    node_out[(size_t)i0 * HD + t] = o0;
    node_out[(size_t)(i0 + 1) * HD + t] = o1;
    node_out[(size_t)(i0 + 2) * HD + t] = o2;
    node_out[(size_t)(i0 + 3) * HD + t] = o3;
}

extern "C" void kernel_launch(void* const* d_in, const int* in_sizes, int n_in,
                              void* d_out, int out_size) {
    const float* x    = (const float*)d_in[0];
    const float* ea   = (const float*)d_in[1];
    const int*   mask = (const int*)d_in[2];
    const float* Wqk  = (const float*)d_in[3];
    const float* We   = (const float*)d_in[4];
    const float* Wv   = (const float*)d_in[5];
    const float* bv   = (const float*)d_in[6];
    const float* Wno  = (const float*)d_in[7];
    const float* bno  = (const float*)d_in[8];
    const float* Weo  = (const float*)d_in[9];
    const float* beo  = (const float*)d_in[10];

    float* out = (float*)d_out;
    float* node_out = out;
    float* edge_out = out + (size_t)Bc * Nc * NODEH;

    cudaFuncSetAttribute(edge_kernel, cudaFuncAttributeMaxDynamicSharedMemorySize, SMEM_EDGE);
    cudaFuncSetAttribute(node_kernel, cudaFuncAttributeMaxDynamicSharedMemorySize,
                         (4 * Hc * Nc + 4 * HD) * (int)sizeof(float));

    prep_qkv_kernel<<<Bc * Nc / 4, 256>>>(x, Wqk, Wv, bv);
    prep_w_kernel<<<KTOT, 160>>>(We, Weo);
    edge_kernel<<<Bc * Nc * 4, 256, SMEM_EDGE>>>(ea, beo, edge_out);
    softmax_kernel<<<Bc * Nc * Hc, 128>>>(mask);
    node_kernel<<<Bc * Nc / 4, 256, (4 * Hc * Nc + 4 * HD) * (int)sizeof(float)>>>(Wno, bno, node_out);
}

// round 11
// speedup vs baseline: 3.1386x; 1.1184x over previous
#include <cuda_runtime.h>
#include <cuda_bf16.h>
#include <cuda_fp16.h>
#include <cstdint>
#include <math.h>

#define Bc 2
#define Nc 512
#define NODEH 256
#define EDGEH 128
#define Hc 8
#define Dc 32
#define HD 256
#define KTOT 384     // EDGEH + HD
#define NB 136       // GEMM N: 128 edge cols + 8 logit cols
#define NKSTEP 24    // KTOT / 16
#define NTILES 17    // NB / 8

// ---------------- scratch globals ----------------
__device__ __align__(16) float g_q[Bc * Nc * HD];
__device__ __align__(16) float g_k[Bc * Nc * HD];
__device__ __align__(16) float g_v[Bc * Nc * HD];
__device__ __align__(16) float g_logits[(size_t)Bc * Nc * Hc * Nc]; // [b,i,h,j]
// W in mma B-fragment layout (single fp16): [kstep][ntile][lane] = {b0, b1}
__device__ __align__(16) uint2 g_WBfrag[NKSTEP * NTILES * 32];

// ---------------- helpers ----------------
__device__ __forceinline__ uint32_t smem_u32(const void* p) {
    uint32_t a;
    asm("{ .reg .u64 t; cvta.to.shared.u64 t, %1; cvt.u32.u64 %0, t; }" : "=r"(a) : "l"(p));
    return a;
}
__device__ __forceinline__ void ldsm4(uint32_t* r, uint32_t addr) {
    asm volatile("ldmatrix.sync.aligned.m8n8.x4.shared.b16 {%0,%1,%2,%3}, [%4];"
        : "=r"(r[0]), "=r"(r[1]), "=r"(r[2]), "=r"(r[3]) : "r"(addr));
}
__device__ __forceinline__ void mma_f16(float* c, const uint32_t* a, uint32_t b0, uint32_t b1) {
    asm volatile("mma.sync.aligned.m16n8k16.row.col.f32.f16.f16.f32 "
        "{%0,%1,%2,%3}, {%4,%5,%6,%7}, {%8,%9}, {%0,%1,%2,%3};"
        : "+f"(c[0]), "+f"(c[1]), "+f"(c[2]), "+f"(c[3])
        : "r"(a[0]), "r"(a[1]), "r"(a[2]), "r"(a[3]), "r"(b0), "r"(b1));
}

// ---------------- edge kernel smem layout (bytes) ----------------
// A plane: 128 rows x 64 k fp16, row stride 144B (128B data + 16B pad)
#define ASTRIDE 144
#define A_OFF 0                         // 18432
#define WS_OFF 18432                    // 17*32*8B*4 ksteps = 17408 -> 35840
#define QS_OFF 35840                    // 256 f32 -> 36864
#define BEO_OFF 36864                   // 128 f32 -> 37376
#define SMEM_EDGE 37376

// ======== 1) q,k,v projection: 4 rows per block ========
__global__ void prep_qkv_kernel(const float* __restrict__ x,
                                const float* __restrict__ Wqk,
                                const float* __restrict__ Wv,
                                const float* __restrict__ bv) {
    __shared__ float xs[4 * NODEH];
    int r0 = blockIdx.x * 4;
    int t = threadIdx.x;
#pragma unroll
    for (int r = 0; r < 4; r++) xs[r * NODEH + t] = x[(size_t)(r0 + r) * NODEH + t];
    __syncthreads();
    float aq[4] = {0, 0, 0, 0}, ak[4] = {0, 0, 0, 0}, av[4] = {0, 0, 0, 0};
#pragma unroll 2
    for (int m = 0; m < NODEH; m++) {
        float wq = Wqk[m * (2 * HD) + t];
        float wk = Wqk[m * (2 * HD) + HD + t];
        float wv = Wv[m * HD + t];
#pragma unroll
        for (int r = 0; r < 4; r++) {
            float xv = xs[r * NODEH + m];
            aq[r] = fmaf(xv, wq, aq[r]);
            ak[r] = fmaf(xv, wk, ak[r]);
            av[r] = fmaf(xv, wv, av[r]);
        }
    }
    float bvt = bv[t];
#pragma unroll
    for (int r = 0; r < 4; r++) {
        g_q[(size_t)(r0 + r) * HD + t] = aq[r];
        g_k[(size_t)(r0 + r) * HD + t] = ak[r];
        g_v[(size_t)(r0 + r) * HD + t] = av[r] + bvt;
    }
}

// ======== 2) W frag pack: B[k][n]; n<128: [Wee;Weo] col; n=128+h: logit col ====
// single fp16 quantization of W
__global__ void prep_w_kernel(const float* __restrict__ We,
                              const float* __restrict__ Weo) {
    __shared__ float wrow[NODEH];
    int k = blockIdx.x;            // 0..383
    int n = threadIdx.x;           // 0..159 (136 active)
    if (k < EDGEH) {
        if (n < 128) { wrow[n] = We[k * NODEH + n]; wrow[n + 128] = We[k * NODEH + n + 128]; }
        __syncthreads();
    }
    if (n >= NB) return;
    float w;
    if (n < 128) {
        if (k < EDGEH) {
            float acc = 0.f;
#pragma unroll 4
            for (int r = 0; r < NODEH; r++) acc = fmaf(wrow[r], Weo[r * EDGEH + n], acc);
            w = acc;                       // (We@Weo)[k][n]
        } else {
            w = Weo[(k - EDGEH) * EDGEH + n];
        }
    } else {
        int h = n - 128;
        if (k < EDGEH) {
            float s = 0.f;
#pragma unroll
            for (int d = 0; d < Dc; d++) s += wrow[h * Dc + d];
            w = s;                         // WeSum[k][h]
        } else {
            w = (((k - EDGEH) >> 5) == h) ? 1.0f : 0.0f;  // indicator for q*k sum
        }
    }
    unsigned short h16 = __half_as_ushort(__float2half_rn(w));
    // fragment placement (m16n8k16 B operand)
    int kstep = k >> 4, kk = k & 15;
    int reg = kk >> 3, tig = (kk & 7) >> 1, kpar = kk & 1;
    int ntile = n >> 3;
    int lane = (n & 7) * 4 + tig;
    size_t base = (((size_t)kstep * NTILES + ntile) * 32 + lane) * 4;
    unsigned short* W16 = (unsigned short*)g_WBfrag;
    W16[base + reg * 2 + kpar] = h16;
}

// ======== 3) edge kernel: HMMA fp16 single-product, logits as N-cols ====
__global__ void __launch_bounds__(256, 2)
edge_kernel(const float* __restrict__ ea,
            const float* __restrict__ beo,
            float* __restrict__ edge_out) {
    extern __shared__ char smem[];
    uint32_t sb = smem_u32(smem);
    int t = threadIdx.x;
    int lane = t & 31;
    int w = t >> 5;                // 0..7
    int blk = blockIdx.x;
    int bi = blk >> 2;             // b*N + i
    int quarter = blk & 3;
    int b = bi >> 9;
    int rg = w >> 1;               // row group 0..3 (32 rows each)
    int cg = w & 1;                // col group
    int ntbase = cg * 8;
    int jg0 = quarter * 128;

    if (t < 256) ((float*)(smem + QS_OFF))[t] = g_q[(size_t)bi * HD + t];
    if (t < 128) ((float*)(smem + BEO_OFF))[t] = beo[t];

    float acc[2][9][4];
#pragma unroll
    for (int mt = 0; mt < 2; mt++)
#pragma unroll
        for (int nt = 0; nt < 9; nt++)
#pragma unroll
            for (int e = 0; e < 4; e++) acc[mt][nt][e] = 0.f;

    // ldmatrix source addresses (x4: 16 rows, two 8-elem k halves)
    uint32_t arow = (uint32_t)(rg * 32 + (lane & 15));
    uint32_t kx = (uint32_t)((lane >> 4) * 16);    // BYTE offset: 8 fp16 = 16B
    uint32_t a_base = sb + A_OFF + arow * ASTRIDE + kx;

    int row_b = t >> 1;            // 0..127
    int kq = t & 1;                // 32-k half

    for (int c = 0; c < 6; c++) {
        // ---- W chunk copy: 4 ksteps of frags -> smem (17408 B) ----
        {
            const uint2* src = g_WBfrag + c * (4 * NTILES * 32);
            uint2* dst = (uint2*)(smem + WS_OFF);
            for (int i = t; i < 4 * NTILES * 32; i += 256) dst[i] = src[i];
        }
        // ---- A build: 128 rows x 64 k, fp16 quantize ----
        {
            float a[32];
            if (c < 2) {
                const float4* s = (const float4*)(ea +
                    ((size_t)(bi * 512 + jg0 + row_b) * EDGEH + c * 64 + kq * 32));
#pragma unroll
                for (int q = 0; q < 8; q++) {
                    float4 v = s[q];
                    a[4 * q] = v.x; a[4 * q + 1] = v.y; a[4 * q + 2] = v.z; a[4 * q + 3] = v.w;
                }
            } else {
                int m0 = (c - 2) * 64 + kq * 32;
                const float4* s = (const float4*)(g_k +
                    (size_t)(b * 512 + jg0 + row_b) * HD + m0);
                const float* qp = (const float*)(smem + QS_OFF) + m0;
#pragma unroll
                for (int q = 0; q < 8; q++) {
                    float4 v = s[q];
                    a[4 * q]     = qp[4 * q]     * v.x;
                    a[4 * q + 1] = qp[4 * q + 1] * v.y;
                    a[4 * q + 2] = qp[4 * q + 2] * v.z;
                    a[4 * q + 3] = qp[4 * q + 3] * v.w;
                }
            }
            uint32_t off = (uint32_t)(row_b * ASTRIDE + kq * 64);
#pragma unroll
            for (int e = 0; e < 32; e += 2) {
                __half2 hp = __floats2half2_rn(a[e], a[e + 1]);
                *(uint32_t*)(smem + A_OFF + off + e * 2) = *reinterpret_cast<uint32_t*>(&hp);
            }
        }
        __syncthreads();
        // ---- MMA over 4 ksteps: acc += A*W ----
#pragma unroll
        for (int ks = 0; ks < 4; ks++) {
            uint32_t a0[4], a1[4];
            ldsm4(a0, a_base + ks * 32);
            ldsm4(a1, a_base + 16 * ASTRIDE + ks * 32);
#pragma unroll
            for (int nt = 0; nt < 9; nt++) {
                if (cg == 0 && nt == 8) continue;   // ntile 8 handled by cg1
                uint2 wb = *(const uint2*)(smem + WS_OFF +
                    (((ks * NTILES) + ntbase + nt) * 32 + lane) * 8);
                mma_f16(acc[0][nt], a0, wb.x, wb.y);
                mma_f16(acc[1][nt], a1, wb.x, wb.y);
            }
        }
        __syncthreads();
    }

    // ---- epilogue ----
    const float* bs = (const float*)(smem + BEO_OFF);
    int jr = rg * 32 + (lane >> 2);
    int cl = (lane & 3) * 2;
    const float isd = 0.17677669529663687f;   // 1/sqrt(32)
#pragma unroll
    for (int mt = 0; mt < 2; mt++) {
        int j = jg0 + jr + mt * 16;
#pragma unroll
        for (int nt = 0; nt < 9; nt++) {
            if (cg == 0 && nt == 8) continue;
            int gnt = ntbase + nt;
            if (gnt < 16) {
                int col = gnt * 8 + cl;
                float2 o0, o1;
                o0.x = acc[mt][nt][0] + bs[col];
                o0.y = acc[mt][nt][1] + bs[col + 1];
                o1.x = acc[mt][nt][2] + bs[col];
                o1.y = acc[mt][nt][3] + bs[col + 1];
                *(float2*)(edge_out + ((size_t)bi * 512 + j) * EDGEH + col) = o0;
                *(float2*)(edge_out + ((size_t)bi * 512 + j + 8) * EDGEH + col) = o1;
            } else {
                int h0 = cl, h1 = cl + 1;
                g_logits[((size_t)bi * Hc + h0) * Nc + j] = acc[mt][nt][0] * isd;
                g_logits[((size_t)bi * Hc + h1) * Nc + j] = acc[mt][nt][1] * isd;
                g_logits[((size_t)bi * Hc + h0) * Nc + j + 8] = acc[mt][nt][2] * isd;
                g_logits[((size_t)bi * Hc + h1) * Nc + j + 8] = acc[mt][nt][3] * isd;
            }
        }
    }
}

// ======== 4) masked softmax over j (mask is int32) ========
__global__ void softmax_kernel(const int* __restrict__ mask) {
    int bih = blockIdx.x;
    int b = bih >> 12;
    float* row = g_logits + (size_t)bih * Nc;
    const int* mrow = mask + b * Nc;
    int t = threadIdx.x;
    float v[4];
    float lmax = -INFINITY;
#pragma unroll
    for (int r = 0; r < 4; r++) {
        int j = t + r * 128;
        float val = row[j];
        if (mrow[j] == 0) val = -3.402823466e38f;
        v[r] = val;
        lmax = fmaxf(lmax, val);
    }
    __shared__ float red[128];
    red[t] = lmax;
    __syncthreads();
    for (int s = 64; s > 0; s >>= 1) {
        if (t < s) red[t] = fmaxf(red[t], red[t + s]);
        __syncthreads();
    }
    float mx = red[0];
    __syncthreads();
    float lsum = 0.f;
#pragma unroll
    for (int r = 0; r < 4; r++) { v[r] = expf(v[r] - mx); lsum += v[r]; }
    red[t] = lsum;
    __syncthreads();
    for (int s = 64; s > 0; s >>= 1) {
        if (t < s) red[t] += red[t + s];
        __syncthreads();
    }
    float inv = 1.0f / red[0];
#pragma unroll
    for (int r = 0; r < 4; r++) row[t + r * 128] = v[r] * inv;
}

// ======== 5) node path: 4 i-rows per block ========
__global__ void node_kernel(const float* __restrict__ Wno,
                            const float* __restrict__ bno,
                            float* __restrict__ node_out) {
    extern __shared__ float ns[];          // att 4*4096 + ctx 4*256
    float* att_s = ns;
    float* ctx_s = ns + 4 * Hc * Nc;
    int i0 = blockIdx.x * 4;
    int b = i0 >> 9;
    int t = threadIdx.x;
    const float* lg = g_logits + (size_t)i0 * Hc * Nc;
    for (int idx = t; idx < 4 * Hc * Nc; idx += 256) att_s[idx] = lg[idx];
    __syncthreads();
    int h = t >> 5;
    const float* vb = g_v + (size_t)b * Nc * HD + t;
    float a0 = 0, a1 = 0, a2 = 0, a3 = 0;
#pragma unroll 2
    for (int j = 0; j < Nc; j++) {
        float v = vb[(size_t)j * HD];
        a0 = fmaf(att_s[h * Nc + j], v, a0);
        a1 = fmaf(att_s[4096 + h * Nc + j], v, a1);
        a2 = fmaf(att_s[8192 + h * Nc + j], v, a2);
        a3 = fmaf(att_s[12288 + h * Nc + j], v, a3);
    }
    ctx_s[t] = a0; ctx_s[256 + t] = a1; ctx_s[512 + t] = a2; ctx_s[768 + t] = a3;
    __syncthreads();
    float bb = bno[t];
    float o0 = bb, o1 = bb, o2 = bb, o3 = bb;
#pragma unroll 2
    for (int m = 0; m < HD; m++) {
        float ww = Wno[m * HD + t];
        o0 = fmaf(ctx_s[m], ww, o0);
        o1 = fmaf(ctx_s[256 + m], ww, o1);
        o2 = fmaf(ctx_s[512 + m], ww, o2);
        o3 = fmaf(ctx_s[768 + m], ww, o3);
    }
    node_out[(size_t)i0 * HD + t] = o0;
    node_out[(size_t)(i0 + 1) * HD + t] = o1;
    node_out[(size_t)(i0 + 2) * HD + t] = o2;
    node_out[(size_t)(i0 + 3) * HD + t] = o3;
}

extern "C" void kernel_launch(void* const* d_in, const int* in_sizes, int n_in,
                              void* d_out, int out_size) {
    const float* x    = (const float*)d_in[0];
    const float* ea   = (const float*)d_in[1];
    const int*   mask = (const int*)d_in[2];
    const float* Wqk  = (const float*)d_in[3];
    const float* We   = (const float*)d_in[4];
    const float* Wv   = (const float*)d_in[5];
    const float* bv   = (const float*)d_in[6];
    const float* Wno  = (const float*)d_in[7];
    const float* bno  = (const float*)d_in[8];
    const float* Weo  = (const float*)d_in[9];
    const float* beo  = (const float*)d_in[10];

    float* out = (float*)d_out;
    float* node_out = out;
    float* edge_out = out + (size_t)Bc * Nc * NODEH;

    cudaFuncSetAttribute(edge_kernel, cudaFuncAttributeMaxDynamicSharedMemorySize, SMEM_EDGE);
    cudaFuncSetAttribute(node_kernel, cudaFuncAttributeMaxDynamicSharedMemorySize,
                         (4 * Hc * Nc + 4 * HD) * (int)sizeof(float));

    prep_qkv_kernel<<<Bc * Nc / 4, 256>>>(x, Wqk, Wv, bv);
    prep_w_kernel<<<KTOT, 160>>>(We, Weo);
    edge_kernel<<<Bc * Nc * 4, 256, SMEM_EDGE>>>(ea, beo, edge_out);
    softmax_kernel<<<Bc * Nc * Hc, 128>>>(mask);
    node_kernel<<<Bc * Nc / 4, 256, (4 * Hc * Nc + 4 * HD) * (int)sizeof(float)>>>(Wno, bno, node_out);
}

// round 12
// speedup vs baseline: 3.6686x; 1.1689x over previous
#include <cuda_runtime.h>
#include <cuda_bf16.h>
#include <cuda_fp16.h>
#include <cstdint>
#include <math.h>

#define Bc 2
#define Nc 512
#define NODEH 256
#define EDGEH 128
#define Hc 8
#define Dc 32
#define HD 256
#define KTOT 384     // EDGEH + HD
#define NB 136       // GEMM N: 128 edge cols + 8 logit cols
#define NKSTEP 24    // KTOT / 16
#define NTILES 17    // NB / 8

// ---------------- scratch globals ----------------
__device__ __align__(16) float g_q[Bc * Nc * HD];
__device__ __align__(16) float g_k[Bc * Nc * HD];
__device__ __align__(16) float g_v[Bc * Nc * HD];
__device__ __align__(16) float g_logits[(size_t)Bc * Nc * Hc * Nc]; // [b,i,h,j]
// W in mma B-fragment layout (single fp16): [kstep][ntile][lane] = {b0, b1}
__device__ __align__(16) uint2 g_WBfrag[NKSTEP * NTILES * 32];
// k pre-packed in mma A-fragment layout: [b][ks(16)][rt(32)][lane(32)] uint4
__device__ __align__(16) uint4 g_kfrag[Bc * 16 * 32 * 32];

// ---------------- helpers ----------------
__device__ __forceinline__ uint32_t smem_u32(const void* p) {
    uint32_t a;
    asm("{ .reg .u64 t; cvta.to.shared.u64 t, %1; cvt.u32.u64 %0, t; }" : "=r"(a) : "l"(p));
    return a;
}
__device__ __forceinline__ void mma_f16(float* c, const uint32_t* a, uint32_t b0, uint32_t b1) {
    asm volatile("mma.sync.aligned.m16n8k16.row.col.f32.f16.f16.f32 "
        "{%0,%1,%2,%3}, {%4,%5,%6,%7}, {%8,%9}, {%0,%1,%2,%3};"
        : "+f"(c[0]), "+f"(c[1]), "+f"(c[2]), "+f"(c[3])
        : "r"(a[0]), "r"(a[1]), "r"(a[2]), "r"(a[3]), "r"(b0), "r"(b1));
}
__device__ __forceinline__ uint32_t h2u(__half2 h) { return *reinterpret_cast<uint32_t*>(&h); }

// ---------------- edge kernel smem layout (bytes) ----------------
#define WS_OFF 0                        // 17*32*8B*4 ksteps = 17408
#define QS_OFF 17408                    // 256 f32 -> 18432
#define BEO_OFF 18432                   // 128 f32 -> 18944
#define SMEM_EDGE 18944

// ======== 1) q,k,v projection: 4 rows per block ========
__global__ void prep_qkv_kernel(const float* __restrict__ x,
                                const float* __restrict__ Wqk,
                                const float* __restrict__ Wv,
                                const float* __restrict__ bv) {
    __shared__ float xs[4 * NODEH];
    int r0 = blockIdx.x * 4;
    int t = threadIdx.x;
#pragma unroll
    for (int r = 0; r < 4; r++) xs[r * NODEH + t] = x[(size_t)(r0 + r) * NODEH + t];
    __syncthreads();
    float aq[4] = {0, 0, 0, 0}, ak[4] = {0, 0, 0, 0}, av[4] = {0, 0, 0, 0};
#pragma unroll 2
    for (int m = 0; m < NODEH; m++) {
        float wq = Wqk[m * (2 * HD) + t];
        float wk = Wqk[m * (2 * HD) + HD + t];
        float wv = Wv[m * HD + t];
#pragma unroll
        for (int r = 0; r < 4; r++) {
            float xv = xs[r * NODEH + m];
            aq[r] = fmaf(xv, wq, aq[r]);
            ak[r] = fmaf(xv, wk, ak[r]);
            av[r] = fmaf(xv, wv, av[r]);
        }
    }
    float bvt = bv[t];
#pragma unroll
    for (int r = 0; r < 4; r++) {
        g_q[(size_t)(r0 + r) * HD + t] = aq[r];
        g_k[(size_t)(r0 + r) * HD + t] = ak[r];
        g_v[(size_t)(r0 + r) * HD + t] = av[r] + bvt;
    }
}

// ======== 2) W frag pack: B[k][n]; n<128: [Wee;Weo] col; n=128+h: logit col ====
__global__ void prep_w_kernel(const float* __restrict__ We,
                              const float* __restrict__ Weo) {
    __shared__ float wrow[NODEH];
    int k = blockIdx.x;            // 0..383
    int n = threadIdx.x;           // 0..159 (136 active)
    if (k < EDGEH) {
        if (n < 128) { wrow[n] = We[k * NODEH + n]; wrow[n + 128] = We[k * NODEH + n + 128]; }
        __syncthreads();
    }
    if (n >= NB) return;
    float w;
    if (n < 128) {
        if (k < EDGEH) {
            float acc = 0.f;
#pragma unroll 4
            for (int r = 0; r < NODEH; r++) acc = fmaf(wrow[r], Weo[r * EDGEH + n], acc);
            w = acc;                       // (We@Weo)[k][n]
        } else {
            w = Weo[(k - EDGEH) * EDGEH + n];
        }
    } else {
        int h = n - 128;
        if (k < EDGEH) {
            float s = 0.f;
#pragma unroll
            for (int d = 0; d < Dc; d++) s += wrow[h * Dc + d];
            w = s;                         // WeSum[k][h]
        } else {
            w = (((k - EDGEH) >> 5) == h) ? 1.0f : 0.0f;  // indicator for q*k sum
        }
    }
    unsigned short h16 = __half_as_ushort(__float2half_rn(w));
    // fragment placement (m16n8k16 B operand)
    int kstep = k >> 4, kk = k & 15;
    int reg = kk >> 3, tig = (kk & 7) >> 1, kpar = kk & 1;
    int ntile = n >> 3;
    int lane = (n & 7) * 4 + tig;
    size_t base = (((size_t)kstep * NTILES + ntile) * 32 + lane) * 4;
    unsigned short* W16 = (unsigned short*)g_WBfrag;
    W16[base + reg * 2 + kpar] = h16;
}

// ======== 2b) k pre-pack into A-fragment fp16 layout ========
// frag (rt, ks, lane): rows r0=rt*16+(lane>>2), r0+8; k c0=ks*16+(lane&3)*2, c0+8
__global__ void pack_k_kernel() {
    int idx = blockIdx.x * 256 + threadIdx.x;   // 32768 total
    int lane = idx & 31;
    int rt = (idx >> 5) & 31;
    int ks = (idx >> 10) & 15;
    int b = idx >> 14;
    int r0 = rt * 16 + (lane >> 2);
    int c0 = ks * 16 + (lane & 3) * 2;
    const float* kb = g_k + ((size_t)b * Nc + r0) * HD + c0;
    float2 p00 = *(const float2*)(kb);
    float2 p10 = *(const float2*)(kb + 8 * HD);
    float2 p01 = *(const float2*)(kb + 8);
    float2 p11 = *(const float2*)(kb + 8 * HD + 8);
    uint4 o;
    o.x = h2u(__floats2half2_rn(p00.x, p00.y));
    o.y = h2u(__floats2half2_rn(p10.x, p10.y));
    o.z = h2u(__floats2half2_rn(p01.x, p01.y));
    o.w = h2u(__floats2half2_rn(p11.x, p11.y));
    g_kfrag[idx] = o;
}

// ======== 3) edge kernel: HMMA fp16, A frags direct, q folded into W ====
__global__ void __launch_bounds__(256, 2)
edge_kernel(const float* __restrict__ ea,
            const float* __restrict__ beo,
            float* __restrict__ edge_out) {
    extern __shared__ char smem[];
    uint32_t sb = smem_u32(smem);
    int t = threadIdx.x;
    int lane = t & 31;
    int w = t >> 5;                // 0..7
    int blk = blockIdx.x;
    int bi = blk >> 2;             // b*N + i
    int quarter = blk & 3;
    int b = bi >> 9;
    int rg = w >> 1;               // row group 0..3 (32 rows each)
    int cg = w & 1;                // col group
    int ntbase = cg * 8;
    int jg0 = quarter * 128;

    if (t < 256) ((float*)(smem + QS_OFF))[t] = g_q[(size_t)bi * HD + t];
    if (t < 128) ((float*)(smem + BEO_OFF))[t] = beo[t];

    float acc[2][9][4];
#pragma unroll
    for (int mt = 0; mt < 2; mt++)
#pragma unroll
        for (int nt = 0; nt < 9; nt++)
#pragma unroll
            for (int e = 0; e < 4; e++) acc[mt][nt][e] = 0.f;

    for (int c = 0; c < 6; c++) {
        // ---- W chunk copy -> smem; chunks >=2 folded with q ----
        if (c < 2) {
            const uint2* src = g_WBfrag + c * (4 * NTILES * 32);
            uint2* dst = (uint2*)(smem + WS_OFF);
            for (int i = t; i < 4 * NTILES * 32; i += 256) dst[i] = src[i];
        } else {
            const uint2* src = g_WBfrag + c * (4 * NTILES * 32);
            uint2* dst = (uint2*)(smem + WS_OFF);
            const float* qbase = (const float*)(smem + QS_OFF) + (c - 2) * 64;
            for (int i = t; i < 4 * NTILES * 32; i += 256) {
                uint2 v = src[i];
                int ksl = i / (NTILES * 32);
                int ln = i & 31;
                int mb = ksl * 16 + (ln & 3) * 2;
                float q0 = qbase[mb], q1 = qbase[mb + 1];
                float q8 = qbase[mb + 8], q9 = qbase[mb + 9];
                float2 xf = __half22float2(*reinterpret_cast<__half2*>(&v.x));
                float2 yf = __half22float2(*reinterpret_cast<__half2*>(&v.y));
                v.x = h2u(__floats2half2_rn(xf.x * q0, xf.y * q1));
                v.y = h2u(__floats2half2_rn(yf.x * q8, yf.y * q9));
                dst[i] = v;
            }
        }
        __syncthreads();

        // ---- MMA over 4 ksteps, A frags loaded directly ----
#pragma unroll
        for (int ks = 0; ks < 4; ks++) {
            uint4 A[2];
            if (c < 2) {
                int c0 = c * 64 + ks * 16 + (lane & 3) * 2;
#pragma unroll
                for (int mt = 0; mt < 2; mt++) {
                    int r0 = jg0 + rg * 32 + mt * 16 + (lane >> 2);
                    const float* eb = ea + ((size_t)bi * Nc + r0) * EDGEH + c0;
                    float2 p00 = *(const float2*)(eb);
                    float2 p10 = *(const float2*)(eb + 8 * EDGEH);
                    float2 p01 = *(const float2*)(eb + 8);
                    float2 p11 = *(const float2*)(eb + 8 * EDGEH + 8);
                    uint4 o;
                    o.x = h2u(__floats2half2_rn(p00.x, p00.y));
                    o.y = h2u(__floats2half2_rn(p10.x, p10.y));
                    o.z = h2u(__floats2half2_rn(p01.x, p01.y));
                    o.w = h2u(__floats2half2_rn(p11.x, p11.y));
                    A[mt] = o;
                }
            } else {
                const uint4* kf = g_kfrag +
                    ((size_t)((b * 16 + (c - 2) * 4 + ks) * 32 + quarter * 8 + rg * 2) * 32 + lane);
                A[0] = kf[0];
                A[1] = kf[32];
            }
#pragma unroll
            for (int nt = 0; nt < 9; nt++) {
                if (cg == 0 && nt == 8) continue;   // ntile 8 handled by cg1
                uint2 wb = *(const uint2*)(smem + WS_OFF +
                    (((ks * NTILES) + ntbase + nt) * 32 + lane) * 8);
                mma_f16(acc[0][nt], (const uint32_t*)&A[0], wb.x, wb.y);
                mma_f16(acc[1][nt], (const uint32_t*)&A[1], wb.x, wb.y);
            }
        }
        __syncthreads();
    }

    // ---- epilogue ----
    const float* bs = (const float*)(smem + BEO_OFF);
    int jr = rg * 32 + (lane >> 2);
    int cl = (lane & 3) * 2;
    const float isd = 0.17677669529663687f;   // 1/sqrt(32)
#pragma unroll
    for (int mt = 0; mt < 2; mt++) {
        int j = jg0 + jr + mt * 16;
#pragma unroll
        for (int nt = 0; nt < 9; nt++) {
            if (cg == 0 && nt == 8) continue;
            int gnt = ntbase + nt;
            if (gnt < 16) {
                int col = gnt * 8 + cl;
                float2 o0, o1;
                o0.x = acc[mt][nt][0] + bs[col];
                o0.y = acc[mt][nt][1] + bs[col + 1];
                o1.x = acc[mt][nt][2] + bs[col];
                o1.y = acc[mt][nt][3] + bs[col + 1];
                *(float2*)(edge_out + ((size_t)bi * Nc + j) * EDGEH + col) = o0;
                *(float2*)(edge_out + ((size_t)bi * Nc + j + 8) * EDGEH + col) = o1;
            } else {
                int h0 = cl, h1 = cl + 1;
                g_logits[((size_t)bi * Hc + h0) * Nc + j] = acc[mt][nt][0] * isd;
                g_logits[((size_t)bi * Hc + h1) * Nc + j] = acc[mt][nt][1] * isd;
                g_logits[((size_t)bi * Hc + h0) * Nc + j + 8] = acc[mt][nt][2] * isd;
                g_logits[((size_t)bi * Hc + h1) * Nc + j + 8] = acc[mt][nt][3] * isd;
            }
        }
    }
}

// ======== 4) masked softmax over j (mask is int32) ========
__global__ void softmax_kernel(const int* __restrict__ mask) {
    int bih = blockIdx.x;
    int b = bih >> 12;
    float* row = g_logits + (size_t)bih * Nc;
    const int* mrow = mask + b * Nc;
    int t = threadIdx.x;
    float v[4];
    float lmax = -INFINITY;
#pragma unroll
    for (int r = 0; r < 4; r++) {
        int j = t + r * 128;
        float val = row[j];
        if (mrow[j] == 0) val = -3.402823466e38f;
        v[r] = val;
        lmax = fmaxf(lmax, val);
    }
    __shared__ float red[128];
    red[t] = lmax;
    __syncthreads();
    for (int s = 64; s > 0; s >>= 1) {
        if (t < s) red[t] = fmaxf(red[t], red[t + s]);
        __syncthreads();
    }
    float mx = red[0];
    __syncthreads();
    float lsum = 0.f;
#pragma unroll
    for (int r = 0; r < 4; r++) { v[r] = expf(v[r] - mx); lsum += v[r]; }
    red[t] = lsum;
    __syncthreads();
    for (int s = 64; s > 0; s >>= 1) {
        if (t < s) red[t] += red[t + s];
        __syncthreads();
    }
    float inv = 1.0f / red[0];
#pragma unroll
    for (int r = 0; r < 4; r++) row[t + r * 128] = v[r] * inv;
}

// ======== 5) node path: 4 i-rows per block ========
__global__ void node_kernel(const float* __restrict__ Wno,
                            const float* __restrict__ bno,
                            float* __restrict__ node_out) {
    extern __shared__ float ns[];          // att 4*4096 + ctx 4*256
    float* att_s = ns;
    float* ctx_s = ns + 4 * Hc * Nc;
    int i0 = blockIdx.x * 4;
    int b = i0 >> 9;
    int t = threadIdx.x;
    const float* lg = g_logits + (size_t)i0 * Hc * Nc;
    for (int idx = t; idx < 4 * Hc * Nc; idx += 256) att_s[idx] = lg[idx];
    __syncthreads();
    int h = t >> 5;
    const float* vb = g_v + (size_t)b * Nc * HD + t;
    float a0 = 0, a1 = 0, a2 = 0, a3 = 0;
#pragma unroll 2
    for (int j = 0; j < Nc; j++) {
        float v = vb[(size_t)j * HD];
        a0 = fmaf(att_s[h * Nc + j], v, a0);
        a1 = fmaf(att_s[4096 + h * Nc + j], v, a1);
        a2 = fmaf(att_s[8192 + h * Nc + j], v, a2);
        a3 = fmaf(att_s[12288 + h * Nc + j], v, a3);
    }
    ctx_s[t] = a0; ctx_s[256 + t] = a1; ctx_s[512 + t] = a2; ctx_s[768 + t] = a3;
    __syncthreads();
    float bb = bno[t];
    float o0 = bb, o1 = bb, o2 = bb, o3 = bb;
#pragma unroll 2
    for (int m = 0; m < HD; m++) {
        float ww = Wno[m * HD + t];
        o0 = fmaf(ctx_s[m], ww, o0);
        o1 = fmaf(ctx_s[256 + m], ww, o1);
        o2 = fmaf(ctx_s[512 + m], ww, o2);
        o3 = fmaf(ctx_s[768 + m], ww, o3);
    }
    node_out[(size_t)i0 * HD + t] = o0;
    node_out[(size_t)(i0 + 1) * HD + t] = o1;
    node_out[(size_t)(i0 + 2) * HD + t] = o2;
    node_out[(size_t)(i0 + 3) * HD + t] = o3;
}

extern "C" void kernel_launch(void* const* d_in, const int* in_sizes, int n_in,
                              void* d_out, int out_size) {
    const float* x    = (const float*)d_in[0];
    const float* ea   = (const float*)d_in[1];
    const int*   mask = (const int*)d_in[2];
    const float* Wqk  = (const float*)d_in[3];
    const float* We   = (const float*)d_in[4];
    const float* Wv   = (const float*)d_in[5];
    const float* bv   = (const float*)d_in[6];
    const float* Wno  = (const float*)d_in[7];
    const float* bno  = (const float*)d_in[8];
    const float* Weo  = (const float*)d_in[9];
    const float* beo  = (const float*)d_in[10];

    float* out = (float*)d_out;
    float* node_out = out;
    float* edge_out = out + (size_t)Bc * Nc * NODEH;

    cudaFuncSetAttribute(edge_kernel, cudaFuncAttributeMaxDynamicSharedMemorySize, SMEM_EDGE);
    cudaFuncSetAttribute(node_kernel, cudaFuncAttributeMaxDynamicSharedMemorySize,
                         (4 * Hc * Nc + 4 * HD) * (int)sizeof(float));

    prep_qkv_kernel<<<Bc * Nc / 4, 256>>>(x, Wqk, Wv, bv);
    prep_w_kernel<<<KTOT, 160>>>(We, Weo);
    pack_k_kernel<<<Bc * 16 * 32 * 32 / 256, 256>>>();
    edge_kernel<<<Bc * Nc * 4, 256, SMEM_EDGE>>>(ea, beo, edge_out);
    softmax_kernel<<<Bc * Nc * Hc, 128>>>(mask);
    node_kernel<<<Bc * Nc / 4, 256, (4 * Hc * Nc + 4 * HD) * (int)sizeof(float)>>>(Wno, bno, node_out);
}

// round 16
// speedup vs baseline: 3.7528x; 1.0230x over previous
#include <cuda_runtime.h>
#include <cuda_bf16.h>
#include <cuda_fp16.h>
#include <cstdint>
#include <math.h>

#define Bc 2
#define Nc 512
#define NODEH 256
#define EDGEH 128
#define Hc 8
#define Dc 32
#define HD 256
#define KTOT 384     // EDGEH + HD
#define NB 136       // GEMM N: 128 edge cols + 8 logit cols
#define NKSTEP 24    // KTOT / 16
#define NTILES 17    // NB / 8

// ---------------- scratch globals ----------------
__device__ __align__(16) float g_q[Bc * Nc * HD];
__device__ __align__(16) float g_k[Bc * Nc * HD];
__device__ __align__(16) float g_v[Bc * Nc * HD];
__device__ __align__(16) float g_logits[(size_t)Bc * Nc * Hc * Nc]; // [b,i,h,j]
// W in mma B-fragment layout (single fp16): [kstep][ntile][lane] = {b0, b1}
__device__ __align__(16) uint2 g_WBfrag[NKSTEP * NTILES * 32];
// k pre-packed in mma A-fragment layout: [b][ks(16)][rt(32)][lane(32)] uint4
__device__ __align__(16) uint4 g_kfrag[Bc * 16 * 32 * 32];

// ---------------- helpers ----------------
__device__ __forceinline__ uint32_t smem_u32(const void* p) {
    uint32_t a;
    asm("{ .reg .u64 t; cvta.to.shared.u64 t, %1; cvt.u32.u64 %0, t; }" : "=r"(a) : "l"(p));
    return a;
}
__device__ __forceinline__ void mma_f16(float* c, const uint32_t* a, uint32_t b0, uint32_t b1) {
    asm volatile("mma.sync.aligned.m16n8k16.row.col.f32.f16.f16.f32 "
        "{%0,%1,%2,%3}, {%4,%5,%6,%7}, {%8,%9}, {%0,%1,%2,%3};"
        : "+f"(c[0]), "+f"(c[1]), "+f"(c[2]), "+f"(c[3])
        : "r"(a[0]), "r"(a[1]), "r"(a[2]), "r"(a[3]), "r"(b0), "r"(b1));
}
__device__ __forceinline__ uint32_t h2u(__half2 h) { return *reinterpret_cast<uint32_t*>(&h); }

#define CP_ASYNC16(dst, src) \
    asm volatile("cp.async.cg.shared.global [%0], [%1], 16;" :: "r"(dst), "l"(src) : "memory")
#define CP_COMMIT() asm volatile("cp.async.commit_group;" ::: "memory")
#define CP_WAIT1()  asm volatile("cp.async.wait_group 1;" ::: "memory")
#define CP_WAIT0()  asm volatile("cp.async.wait_group 0;" ::: "memory")

// ---------------- edge kernel smem layout (bytes) ----------------
// ea chunk buffers: 128 rows x 272B (256B data + 16B pad), 2 buffers
#define EASTRIDE 272
#define EACHUNK 34816                   // 128 * 272
#define EA_OFF 0                        // 2 x 34816 = 69632
#define WS_OFF 69632                    // 17*32*8B*4 ksteps = 17408 -> 87040
#define QS_OFF 87040                    // 256 f32 -> 88064
#define BEO_OFF 88064                   // 128 f32 -> 88576
#define SMEM_EDGE 88576

// ======== 1) q,k,v projection: 4 rows per block ========
__global__ void prep_qkv_kernel(const float* __restrict__ x,
                                const float* __restrict__ Wqk,
                                const float* __restrict__ Wv,
                                const float* __restrict__ bv) {
    __shared__ float xs[4 * NODEH];
    int r0 = blockIdx.x * 4;
    int t = threadIdx.x;
#pragma unroll
    for (int r = 0; r < 4; r++) xs[r * NODEH + t] = x[(size_t)(r0 + r) * NODEH + t];
    __syncthreads();
    float aq[4] = {0, 0, 0, 0}, ak[4] = {0, 0, 0, 0}, av[4] = {0, 0, 0, 0};
#pragma unroll 2
    for (int m = 0; m < NODEH; m++) {
        float wq = Wqk[m * (2 * HD) + t];
        float wk = Wqk[m * (2 * HD) + HD + t];
        float wv = Wv[m * HD + t];
#pragma unroll
        for (int r = 0; r < 4; r++) {
            float xv = xs[r * NODEH + m];
            aq[r] = fmaf(xv, wq, aq[r]);
            ak[r] = fmaf(xv, wk, ak[r]);
            av[r] = fmaf(xv, wv, av[r]);
        }
    }
    float bvt = bv[t];
#pragma unroll
    for (int r = 0; r < 4; r++) {
        g_q[(size_t)(r0 + r) * HD + t] = aq[r];
        g_k[(size_t)(r0 + r) * HD + t] = ak[r];
        g_v[(size_t)(r0 + r) * HD + t] = av[r] + bvt;
    }
}

// ======== 2) W frag pack: B[k][n]; n<128: [Wee;Weo] col; n=128+h: logit col ====
__global__ void prep_w_kernel(const float* __restrict__ We,
                              const float* __restrict__ Weo) {
    __shared__ float wrow[NODEH];
    int k = blockIdx.x;            // 0..383
    int n = threadIdx.x;           // 0..159 (136 active)
    if (k < EDGEH) {
        if (n < 128) { wrow[n] = We[k * NODEH + n]; wrow[n + 128] = We[k * NODEH + n + 128]; }
        __syncthreads();
    }
    if (n >= NB) return;
    float w;
    if (n < 128) {
        if (k < EDGEH) {
            float acc = 0.f;
#pragma unroll 4
            for (int r = 0; r < NODEH; r++) acc = fmaf(wrow[r], Weo[r * EDGEH + n], acc);
            w = acc;                       // (We@Weo)[k][n]
        } else {
            w = Weo[(k - EDGEH) * EDGEH + n];
        }
    } else {
        int h = n - 128;
        if (k < EDGEH) {
            float s = 0.f;
#pragma unroll
            for (int d = 0; d < Dc; d++) s += wrow[h * Dc + d];
            w = s;                         // WeSum[k][h]
        } else {
            w = (((k - EDGEH) >> 5) == h) ? 1.0f : 0.0f;  // indicator for q*k sum
        }
    }
    unsigned short h16 = __half_as_ushort(__float2half_rn(w));
    // fragment placement (m16n8k16 B operand)
    int kstep = k >> 4, kk = k & 15;
    int reg = kk >> 3, tig = (kk & 7) >> 1, kpar = kk & 1;
    int ntile = n >> 3;
    int lane = (n & 7) * 4 + tig;
    size_t base = (((size_t)kstep * NTILES + ntile) * 32 + lane) * 4;
    unsigned short* W16 = (unsigned short*)g_WBfrag;
    W16[base + reg * 2 + kpar] = h16;
}

// ======== 2b) k pre-pack into A-fragment fp16 layout ========
__global__ void pack_k_kernel() {
    int idx = blockIdx.x * 256 + threadIdx.x;   // 32768 total
    int lane = idx & 31;
    int rt = (idx >> 5) & 31;
    int ks = (idx >> 10) & 15;
    int b = idx >> 14;
    int r0 = rt * 16 + (lane >> 2);
    int c0 = ks * 16 + (lane & 3) * 2;
    const float* kb = g_k + ((size_t)b * Nc + r0) * HD + c0;
    float2 p00 = *(const float2*)(kb);
    float2 p10 = *(const float2*)(kb + 8 * HD);
    float2 p01 = *(const float2*)(kb + 8);
    float2 p11 = *(const float2*)(kb + 8 * HD + 8);
    uint4 o;
    o.x = h2u(__floats2half2_rn(p00.x, p00.y));
    o.y = h2u(__floats2half2_rn(p10.x, p10.y));
    o.z = h2u(__floats2half2_rn(p01.x, p01.y));
    o.w = h2u(__floats2half2_rn(p11.x, p11.y));
    g_kfrag[idx] = o;
}

// ======== 3) edge kernel: HMMA fp16, ea staged via cp.async, q folded into W ====
__global__ void __launch_bounds__(256, 2)
edge_kernel(const float* __restrict__ ea,
            const float* __restrict__ beo,
            float* __restrict__ edge_out) {
    extern __shared__ char smem[];
    uint32_t sb = smem_u32(smem);
    int t = threadIdx.x;
    int lane = t & 31;
    int w = t >> 5;                // 0..7
    int blk = blockIdx.x;
    int bi = blk >> 2;             // b*N + i
    int quarter = blk & 3;
    int b = bi >> 9;
    int rg = w >> 1;               // row group 0..3 (32 rows each)
    int cg = w & 1;                // col group
    int ntbase = cg * 8;
    int jg0 = quarter * 128;

    // ---- prefetch both ea chunks into smem (deep-MLP cp.async) ----
#pragma unroll
    for (int c = 0; c < 2; c++) {
#pragma unroll
        for (int it = 0; it < 8; it++) {
            int idx = t + it * 256;
            int row = idx >> 4, seg = idx & 15;
            uint32_t dst = sb + EA_OFF + c * EACHUNK + row * EASTRIDE + seg * 16;
            const float* src = ea + ((size_t)(bi * 512 + jg0 + row) * EDGEH + c * 64 + seg * 4);
            CP_ASYNC16(dst, src);
        }
        CP_COMMIT();
    }

    ((float*)(smem + QS_OFF))[t] = g_q[(size_t)bi * HD + t];
    if (t < 128) ((float*)(smem + BEO_OFF))[t] = beo[t];

    float acc[2][9][4];
#pragma unroll
    for (int mt = 0; mt < 2; mt++)
#pragma unroll
        for (int nt = 0; nt < 9; nt++)
#pragma unroll
            for (int e = 0; e < 4; e++) acc[mt][nt][e] = 0.f;

    for (int c = 0; c < 6; c++) {
        // ---- W chunk copy -> smem; chunks >=2 folded with q ----
        if (c < 2) {
            const uint2* src = g_WBfrag + c * (4 * NTILES * 32);
            uint2* dst = (uint2*)(smem + WS_OFF);
            for (int i = t; i < 4 * NTILES * 32; i += 256) dst[i] = src[i];
        } else {
            const uint2* src = g_WBfrag + c * (4 * NTILES * 32);
            uint2* dst = (uint2*)(smem + WS_OFF);
            const float* qbase = (const float*)(smem + QS_OFF) + (c - 2) * 64;
            for (int i = t; i < 4 * NTILES * 32; i += 256) {
                uint2 v = src[i];
                int ksl = i / (NTILES * 32);
                int ln = i & 31;
                int mb = ksl * 16 + (ln & 3) * 2;
                float q0 = qbase[mb], q1 = qbase[mb + 1];
                float q8 = qbase[mb + 8], q9 = qbase[mb + 9];
                float2 xf = __half22float2(*reinterpret_cast<__half2*>(&v.x));
                float2 yf = __half22float2(*reinterpret_cast<__half2*>(&v.y));
                v.x = h2u(__floats2half2_rn(xf.x * q0, xf.y * q1));
                v.y = h2u(__floats2half2_rn(yf.x * q8, yf.y * q9));
                dst[i] = v;
            }
        }
        if (c == 0) { CP_WAIT1(); }
        else if (c == 1) { CP_WAIT0(); }
        __syncthreads();

        // ---- MMA over 4 ksteps ----
#pragma unroll
        for (int ks = 0; ks < 4; ks++) {
            uint4 A[2];
            if (c < 2) {
                const char* ebase = smem + EA_OFF + c * EACHUNK
                    + (rg * 32 + (lane >> 2)) * EASTRIDE + (ks * 16 + (lane & 3) * 2) * 4;
#pragma unroll
                for (int mt = 0; mt < 2; mt++) {
                    const char* p = ebase + mt * 16 * EASTRIDE;
                    float2 p00 = *(const float2*)(p);
                    float2 p10 = *(const float2*)(p + 8 * EASTRIDE);
                    float2 p01 = *(const float2*)(p + 32);
                    float2 p11 = *(const float2*)(p + 8 * EASTRIDE + 32);
                    uint4 o;
                    o.x = h2u(__floats2half2_rn(p00.x, p00.y));
                    o.y = h2u(__floats2half2_rn(p10.x, p10.y));
                    o.z = h2u(__floats2half2_rn(p01.x, p01.y));
                    o.w = h2u(__floats2half2_rn(p11.x, p11.y));
                    A[mt] = o;
                }
            } else {
                const uint4* kf = g_kfrag +
                    ((size_t)((b * 16 + (c - 2) * 4 + ks) * 32 + quarter * 8 + rg * 2) * 32 + lane);
                A[0] = kf[0];
                A[1] = kf[32];
            }
#pragma unroll
            for (int nt = 0; nt < 9; nt++) {
                if (cg == 0 && nt == 8) continue;   // ntile 8 handled by cg1
                uint2 wb = *(const uint2*)(smem + WS_OFF +
                    (((ks * NTILES) + ntbase + nt) * 32 + lane) * 8);
                mma_f16(acc[0][nt], (const uint32_t*)&A[0], wb.x, wb.y);
                mma_f16(acc[1][nt], (const uint32_t*)&A[1], wb.x, wb.y);
            }
        }
        __syncthreads();
    }

    // ---- epilogue ----
    const float* bs = (const float*)(smem + BEO_OFF);
    int jr = rg * 32 + (lane >> 2);
    int cl = (lane & 3) * 2;
    const float isd = 0.17677669529663687f;   // 1/sqrt(32)
#pragma unroll
    for (int mt = 0; mt < 2; mt++) {
        int j = jg0 + jr + mt * 16;
#pragma unroll
        for (int nt = 0; nt < 9; nt++) {
            if (cg == 0 && nt == 8) continue;
            int gnt = ntbase + nt;
            if (gnt < 16) {
                int col = gnt * 8 + cl;
                float2 o0, o1;
                o0.x = acc[mt][nt][0] + bs[col];
                o0.y = acc[mt][nt][1] + bs[col + 1];
                o1.x = acc[mt][nt][2] + bs[col];
                o1.y = acc[mt][nt][3] + bs[col + 1];
                *(float2*)(edge_out + ((size_t)bi * Nc + j) * EDGEH + col) = o0;
                *(float2*)(edge_out + ((size_t)bi * Nc + j + 8) * EDGEH + col) = o1;
            } else {
                int h0 = cl, h1 = cl + 1;
                g_logits[((size_t)bi * Hc + h0) * Nc + j] = acc[mt][nt][0] * isd;
                g_logits[((size_t)bi * Hc + h1) * Nc + j] = acc[mt][nt][1] * isd;
                g_logits[((size_t)bi * Hc + h0) * Nc + j + 8] = acc[mt][nt][2] * isd;
                g_logits[((size_t)bi * Hc + h1) * Nc + j + 8] = acc[mt][nt][3] * isd;
            }
        }
    }
}

// ======== 4) masked softmax over j (mask is int32) ========
__global__ void softmax_kernel(const int* __restrict__ mask) {
    int bih = blockIdx.x;
    int b = bih >> 12;
    float* row = g_logits + (size_t)bih * Nc;
    const int* mrow = mask + b * Nc;
    int t = threadIdx.x;
    float v[4];
    float lmax = -INFINITY;
#pragma unroll
    for (int r = 0; r < 4; r++) {
        int j = t + r * 128;
        float val = row[j];
        if (mrow[j] == 0) val = -3.402823466e38f;
        v[r] = val;
        lmax = fmaxf(lmax, val);
    }
    __shared__ float red[128];
    red[t] = lmax;
    __syncthreads();
    for (int s = 64; s > 0; s >>= 1) {
        if (t < s) red[t] = fmaxf(red[t], red[t + s]);
        __syncthreads();
    }
    float mx = red[0];
    __syncthreads();
    float lsum = 0.f;
#pragma unroll
    for (int r = 0; r < 4; r++) { v[r] = expf(v[r] - mx); lsum += v[r]; }
    red[t] = lsum;
    __syncthreads();
    for (int s = 64; s > 0; s >>= 1) {
        if (t < s) red[t] += red[t + s];
        __syncthreads();
    }
    float inv = 1.0f / red[0];
#pragma unroll
    for (int r = 0; r < 4; r++) row[t + r * 128] = v[r] * inv;
}

// ======== 5) node path: 4 i-rows per block ========
__global__ void node_kernel(const float* __restrict__ Wno,
                            const float* __restrict__ bno,
                            float* __restrict__ node_out) {
    extern __shared__ float ns[];          // att 4*4096 + ctx 4*256
    float* att_s = ns;
    float* ctx_s = ns + 4 * Hc * Nc;
    int i0 = blockIdx.x * 4;
    int b = i0 >> 9;
    int t = threadIdx.x;
    const float* lg = g_logits + (size_t)i0 * Hc * Nc;
    for (int idx = t; idx < 4 * Hc * Nc; idx += 256) att_s[idx] = lg[idx];
    __syncthreads();
    int h = t >> 5;
    const float* vb = g_v + (size_t)b * Nc * HD + t;
    float a0 = 0, a1 = 0, a2 = 0, a3 = 0;
#pragma unroll 2
    for (int j = 0; j < Nc; j++) {
        float v = vb[(size_t)j * HD];
        a0 = fmaf(att_s[h * Nc + j], v, a0);
        a1 = fmaf(att_s[4096 + h * Nc + j], v, a1);
        a2 = fmaf(att_s[8192 + h * Nc + j], v, a2);
        a3 = fmaf(att_s[12288 + h * Nc + j], v, a3);
    }
    ctx_s[t] = a0; ctx_s[256 + t] = a1; ctx_s[512 + t] = a2; ctx_s[768 + t] = a3;
    __syncthreads();
    float bb = bno[t];
    float o0 = bb, o1 = bb, o2 = bb, o3 = bb;
#pragma unroll 2
    for (int m = 0; m < HD; m++) {
        float ww = Wno[m * HD + t];
        o0 = fmaf(ctx_s[m], ww, o0);
        o1 = fmaf(ctx_s[256 + m], ww, o1);
        o2 = fmaf(ctx_s[512 + m], ww, o2);
        o3 = fmaf(ctx_s[768 + m], ww, o3);
    }
    node_out[(size_t)i0 * HD + t] = o0;
    node_out[(size_t)(i0 + 1) * HD + t] = o1;
    node_out[(size_t)(i0 + 2) * HD + t] = o2;
    node_out[(size_t)(i0 + 3) * HD + t] = o3;
}

extern "C" void kernel_launch(void* const* d_in, const int* in_sizes, int n_in,
                              void* d_out, int out_size) {
    const float* x    = (const float*)d_in[0];
    const float* ea   = (const float*)d_in[1];
    const int*   mask = (const int*)d_in[2];
    const float* Wqk  = (const float*)d_in[3];
    const float* We   = (const float*)d_in[4];
    const float* Wv   = (const float*)d_in[5];
    const float* bv   = (const float*)d_in[6];
    const float* Wno  = (const float*)d_in[7];
    const float* bno  = (const float*)d_in[8];
    const float* Weo  = (const float*)d_in[9];
    const float* beo  = (const float*)d_in[10];

    float* out = (float*)d_out;
    float* node_out = out;
    float* edge_out = out + (size_t)Bc * Nc * NODEH;

    cudaFuncSetAttribute(edge_kernel, cudaFuncAttributeMaxDynamicSharedMemorySize, SMEM_EDGE);
    cudaFuncSetAttribute(node_kernel, cudaFuncAttributeMaxDynamicSharedMemorySize,
                         (4 * Hc * Nc + 4 * HD) * (int)sizeof(float));

    prep_qkv_kernel<<<Bc * Nc / 4, 256>>>(x, Wqk, Wv, bv);
    prep_w_kernel<<<KTOT, 160>>>(We, Weo);
    pack_k_kernel<<<Bc * 16 * 32 * 32 / 256, 256>>>();
    edge_kernel<<<Bc * Nc * 4, 256, SMEM_EDGE>>>(ea, beo, edge_out);
    softmax_kernel<<<Bc * Nc * Hc, 128>>>(mask);
    node_kernel<<<Bc * Nc / 4, 256, (4 * Hc * Nc + 4 * HD) * (int)sizeof(float)>>>(Wno, bno, node_out);
}